// round 11
// baseline (speedup 1.0000x reference)
#include <cuda_runtime.h>
#include <cuda_bf16.h>
#include <cuda_fp16.h>
#include <cstdint>
#include <math.h>

#define Nn   50000
#define Ee   800000
#define ETOT 850000
#define HC   256
#define CH   128

typedef __half f16;

// ---------------- static device scratch ----------------
__device__ __align__(16) f16   g_ax[(size_t)Nn * 256];     // x ext [Ah|Al]
__device__ __align__(16) f16   g_aext[(size_t)Nn * 512];   // h ext [Ah|Al]
__device__ __align__(16) f16   g_midext[(size_t)Nn * 128]; // mid ext
__device__ __align__(16) float g_h1[(size_t)Nn * HC];
__device__ __align__(16) f16   g_b1e[256 * 256];   // [Bh;Bh] for W1
__device__ __align__(16) f16   g_b2e[512 * 256];
__device__ __align__(16) f16   g_b3e[512 * 64];
__device__ __align__(16) f16   g_b4e[128 * 128];
__device__ float g_as[Nn * 4];
__device__ float g_ad[Nn * 4];
__device__ int   g_cnt[Nn];
__device__ int   g_incl[Nn];
__device__ int   g_bsum[64];
__device__ int   g_rowptr[Nn + 1];
__device__ int   g_csrc[ETOT];
__device__ int   g_is64;

// ---------------- edge-index dtype detection ----------------
__global__ void k_detect(const long long* ei) {
    __shared__ int bad;
    if (threadIdx.x == 0) bad = 0;
    __syncthreads();
    long long v = ei[threadIdx.x];
    if (v < 0 || v >= Nn) atomicExch(&bad, 1);
    __syncthreads();
    if (threadIdx.x == 0) g_is64 = bad ? 0 : 1;
}

__device__ __forceinline__ int edge_at(const void* ei, int which, int i) {
    if (g_is64) return (int)((const long long*)ei)[(size_t)which * Ee + i];
    return ((const int*)ei)[(size_t)which * Ee + i];
}

// ---------------- CSR build ----------------
__global__ void k_hist(const void* ei) {
    int i = blockIdx.x * blockDim.x + threadIdx.x;
    if (i >= ETOT) return;
    int d = (i < Ee) ? edge_at(ei, 1, i) : (i - Ee);
    atomicAdd(&g_cnt[d], 1);
}

__global__ void k_scan_block() {
    __shared__ int sh[1024];
    int i = blockIdx.x * 1024 + threadIdx.x;
    int v = (i < Nn) ? g_cnt[i] : 0;
    sh[threadIdx.x] = v;
    __syncthreads();
    for (int off = 1; off < 1024; off <<= 1) {
        int t = (threadIdx.x >= off) ? sh[threadIdx.x - off] : 0;
        __syncthreads();
        sh[threadIdx.x] += t;
        __syncthreads();
    }
    if (i < Nn) g_incl[i] = sh[threadIdx.x];
    if (threadIdx.x == 1023) g_bsum[blockIdx.x] = sh[1023];
}

__global__ void k_scan_bsum(int nb) {
    __shared__ int sh[64];
    int v = (threadIdx.x < nb) ? g_bsum[threadIdx.x] : 0;
    sh[threadIdx.x] = v;
    __syncthreads();
    for (int off = 1; off < 64; off <<= 1) {
        int t = (threadIdx.x >= off) ? sh[threadIdx.x - off] : 0;
        __syncthreads();
        sh[threadIdx.x] += t;
        __syncthreads();
    }
    if (threadIdx.x < nb) g_bsum[threadIdx.x] = sh[threadIdx.x];
}

__global__ void k_scan_add() {
    int i = blockIdx.x * 1024 + threadIdx.x;
    if (i < Nn) {
        int add = blockIdx.x ? g_bsum[blockIdx.x - 1] : 0;
        g_rowptr[i + 1] = g_incl[i] + add;
        if (i == 0) g_rowptr[0] = 0;
    }
}

__global__ void k_scatter(const void* ei) {
    int i = blockIdx.x * blockDim.x + threadIdx.x;
    if (i >= ETOT) return;
    int s, d;
    if (i < Ee) { s = edge_at(ei, 0, i); d = edge_at(ei, 1, i); }
    else        { s = d = i - Ee; }
    int pos = g_rowptr[d] + atomicAdd(&g_cnt[d], 1);
    g_csrc[pos] = s;
}

// ---------------- split-fp16 conversions ----------------
__device__ __forceinline__ void split_h(float v, f16& hi, f16& lo) {
    hi = __float2half(v);
    lo = __float2half(v - __half2float(hi));
}

// A ext: cols [0,K)=hi, [K,2K)=lo
__global__ void k_convA(const float* __restrict__ X, f16* __restrict__ out, int M, int K) {
    int idx = blockIdx.x * blockDim.x + threadIdx.x;
    if (idx >= M * K) return;
    int m = idx / K, k = idx % K;
    f16 hi, lo;
    split_h(X[idx], hi, lo);
    size_t base = (size_t)m * (2 * K);
    out[base + k] = hi;
    out[base + K + k] = lo;
}

// B ext: rows [0,K)=hi, [K,2K)=hi (duplicated); pad cols to Nphys
__global__ void k_convB(const float* __restrict__ W, f16* __restrict__ out,
                        int K, int Nsrc, int Nphys) {
    int idx = blockIdx.x * blockDim.x + threadIdx.x;
    if (idx >= K * Nphys) return;
    int k = idx / Nphys, n = idx % Nphys;
    float v = (n < Nsrc) ? W[k * Nsrc + n] : 0.f;
    f16 hi = __float2half(v);
    out[(size_t)k * Nphys + n] = hi;
    out[(size_t)(K + k) * Nphys + n] = hi;
}

// ---------------- single-pass online-softmax aggregation ----------------
__global__ __launch_bounds__(128)
void k_agg3(const float* __restrict__ h,
            const float* __restrict__ bias,
            f16* __restrict__ outext) {
    int n = blockIdx.x;
    int tid = threadIdx.x;
    int w = tid >> 5, l = tid & 31;
    int beg = g_rowptr[n], end = g_rowptr[n + 1];
    float adv = g_ad[n * 4 + w];

    __shared__ int   s_src[CH];
    __shared__ float s_t[CH][4];

    float acc0 = 0.f, acc1 = 0.f, den = 0.f, m = -1e30f;

    for (int c0 = beg; c0 < end; c0 += CH) {
        int cnt = min(CH, end - c0);
        __syncthreads();
        for (int i = tid; i < cnt; i += 128) s_src[i] = g_csrc[c0 + i];
        __syncthreads();

        float cm = -1e30f;
        for (int i = l; i < cnt; i += 32) {
            float t = g_as[s_src[i] * 4 + w] + adv;
            t = (t > 0.f) ? t : 0.2f * t;
            s_t[i][w] = t;
            cm = fmaxf(cm, t);
        }
        for (int o = 16; o; o >>= 1) cm = fmaxf(cm, __shfl_xor_sync(0xffffffffu, cm, o));
        __syncwarp();

        float nm = fmaxf(m, cm);
        float sc = __expf(m - nm);
        acc0 *= sc; acc1 *= sc; den *= sc;
        m = nm;

#pragma unroll 4
        for (int e = 0; e < cnt; e++) {
            float wt = __expf(s_t[e][w] - m);
            den += wt;
            float2 v = *(const float2*)(h + (size_t)s_src[e] * HC + w * 64 + 2 * l);
            acc0 += wt * v.x;
            acc1 += wt * v.y;
        }
    }

    float inv = 1.f / (den + 1e-16f);
    int c0 = w * 64 + 2 * l, c1 = c0 + 1;
    float v0 = fmaxf(acc0 * inv + bias[c0], 0.f);
    float v1 = fmaxf(acc1 * inv + bias[c1], 0.f);
    f16 h0, l0, h1b, l1;
    split_h(v0, h0, l0);
    split_h(v1, h1b, l1);
    size_t base = (size_t)n * 512;
    outext[base + c0] = h0;  outext[base + 256 + c0] = l0;
    outext[base + c1] = h1b; outext[base + 256 + c1] = l1;
}

// ---------------- mma helpers (fp16) ----------------
__device__ __forceinline__ unsigned smem_u32(const void* p) {
    return (unsigned)__cvta_generic_to_shared(p);
}
__device__ __forceinline__ void ldsm4(unsigned addr, unsigned& r0, unsigned& r1,
                                      unsigned& r2, unsigned& r3) {
    asm volatile("ldmatrix.sync.aligned.m8n8.x4.shared.b16 {%0,%1,%2,%3},[%4];"
                 : "=r"(r0), "=r"(r1), "=r"(r2), "=r"(r3) : "r"(addr));
}
__device__ __forceinline__ void ldsm4t(unsigned addr, unsigned& r0, unsigned& r1,
                                       unsigned& r2, unsigned& r3) {
    asm volatile("ldmatrix.sync.aligned.m8n8.x4.trans.shared.b16 {%0,%1,%2,%3},[%4];"
                 : "=r"(r0), "=r"(r1), "=r"(r2), "=r"(r3) : "r"(addr));
}
__device__ __forceinline__ void mma16816(float& c0, float& c1, float& c2, float& c3,
                                         unsigned a0, unsigned a1, unsigned a2, unsigned a3,
                                         unsigned b0, unsigned b1) {
    asm volatile("mma.sync.aligned.m16n8k16.row.col.f32.f16.f16.f32 "
                 "{%0,%1,%2,%3},{%4,%5,%6,%7},{%8,%9},{%0,%1,%2,%3};"
                 : "+f"(c0), "+f"(c1), "+f"(c2), "+f"(c3)
                 : "r"(a0), "r"(a1), "r"(a2), "r"(a3), "r"(b0), "r"(b1));
}
__device__ __forceinline__ void cp16(unsigned dst, const void* src) {
    asm volatile("cp.async.cg.shared.global [%0], [%1], 16;" :: "r"(dst), "l"(src));
}
__device__ __forceinline__ void cp_commit() {
    asm volatile("cp.async.commit_group;" ::: "memory");
}
__device__ __forceinline__ void cp_wait1() {
    asm volatile("cp.async.wait_group 1;" ::: "memory");
}

// ---------------- 128x256 3-stage cp.async fp16 GEMM + fused attention dots ----------------
// 512 threads, 16 warps: 4 along M x 4 along N, 32x64 per warp. fp32 out.
__global__ __launch_bounds__(512)
void k_g256(const f16* __restrict__ A, const f16* __restrict__ B,
            float* __restrict__ C, int M, int Kext,
            const float* __restrict__ asrc, const float* __restrict__ adst,
            float* __restrict__ gas, float* __restrict__ gad) {
    constexpr int LDA = 40;
    constexpr int LDB = 264;
    constexpr int ASZ = 128 * LDA;
    constexpr int BSZ = 32 * LDB;

    extern __shared__ f16 sm[];
    f16* As = sm;
    f16* Bs = sm + 3 * ASZ;

    const int tid = threadIdx.x;
    const int warp = tid >> 5, lane = tid & 31;
    const int wm = warp & 3, wn = warp >> 2;
    const int warpRow = wm * 32;
    const int warpCol = wn * 64;
    const int rowBase = blockIdx.y * 128;

    float acc[2][8][4];
#pragma unroll
    for (int i = 0; i < 2; i++)
#pragma unroll
        for (int j = 0; j < 8; j++)
#pragma unroll
            for (int q = 0; q < 4; q++) acc[i][j][q] = 0.f;

    const int nsteps = Kext / 32;
    const int arow = tid >> 2, aq = tid & 3;

    auto load_stage = [&](int st, int k0) {
        unsigned abase = smem_u32(&As[st * ASZ]);
        unsigned bbase = smem_u32(&Bs[st * BSZ]);
        {
            int gr = min(rowBase + arow, M - 1);
            cp16(abase + (arow * LDA + aq * 8) * 2,
                 A + (size_t)gr * Kext + k0 + aq * 8);
        }
#pragma unroll
        for (int i = 0; i < 2; i++) {
            int idx = tid + i * 512;
            int k = idx >> 5, qb = idx & 31;
            cp16(bbase + (k * LDB + qb * 8) * 2,
                 B + (size_t)(k0 + k) * 256 + qb * 8);
        }
    };

    load_stage(0, 0);
    cp_commit();
    if (1 < nsteps) load_stage(1, 32);
    cp_commit();
    cp_wait1();
    __syncthreads();

    for (int s = 0; s < nsteps; ++s) {
        int buf = s % 3;
        unsigned aB = smem_u32(&As[buf * ASZ]);
        unsigned bB = smem_u32(&Bs[buf * BSZ]);

#pragma unroll
        for (int ks = 0; ks < 32; ks += 16) {
            unsigned a[2][4];
#pragma unroll
            for (int mf = 0; mf < 2; mf++) {
                int row = warpRow + mf * 16 + (lane & 15);
                int col = ks + ((lane & 16) ? 8 : 0);
                ldsm4(aB + (row * LDA + col) * 2, a[mf][0], a[mf][1], a[mf][2], a[mf][3]);
            }
            unsigned bb[8][2];
#pragma unroll
            for (int g = 0; g < 4; g++) {
                int kk = ks + (lane & 15);
                int nn = warpCol + g * 16 + ((lane & 16) ? 8 : 0);
                unsigned r0, r1, r2, r3;
                ldsm4t(bB + (kk * LDB + nn) * 2, r0, r1, r2, r3);
                bb[2 * g][0] = r0; bb[2 * g][1] = r1;
                bb[2 * g + 1][0] = r2; bb[2 * g + 1][1] = r3;
            }
#pragma unroll
            for (int mf = 0; mf < 2; mf++)
#pragma unroll
                for (int nf = 0; nf < 8; nf++)
                    mma16816(acc[mf][nf][0], acc[mf][nf][1], acc[mf][nf][2], acc[mf][nf][3],
                             a[mf][0], a[mf][1], a[mf][2], a[mf][3],
                             bb[nf][0], bb[nf][1]);
        }

        int nx = s + 2;
        if (nx < nsteps) load_stage(nx % 3, nx * 32);
        cp_commit();
        cp_wait1();
        __syncthreads();
    }

    // ---- epilogue: C stores ----
#pragma unroll
    for (int mf = 0; mf < 2; mf++) {
#pragma unroll
        for (int nf = 0; nf < 8; nf++) {
            int gr0 = rowBase + warpRow + mf * 16 + (lane >> 2);
            int gc  = warpCol + nf * 8 + (lane & 3) * 2;
#pragma unroll
            for (int half = 0; half < 2; half++) {
                int gr = gr0 + half * 8;
                if (gr >= M) continue;
                float2 v = make_float2(acc[mf][nf][half * 2], acc[mf][nf][half * 2 + 1]);
                *(float2*)(C + (size_t)gr * 256 + gc) = v;
            }
        }
    }

    // ---- fused attention dot products ----
    float av[16], dv[16];
#pragma unroll
    for (int nf = 0; nf < 8; nf++) {
        int gc = warpCol + nf * 8 + (lane & 3) * 2;
        av[nf * 2 + 0] = asrc[gc];     av[nf * 2 + 1] = asrc[gc + 1];
        dv[nf * 2 + 0] = adst[gc];     dv[nf * 2 + 1] = adst[gc + 1];
    }
#pragma unroll
    for (int mf = 0; mf < 2; mf++) {
#pragma unroll
        for (int half = 0; half < 2; half++) {
            int gr = rowBase + warpRow + mf * 16 + (lane >> 2) + half * 8;
            float s = 0.f, d = 0.f;
#pragma unroll
            for (int nf = 0; nf < 8; nf++) {
                float v0 = acc[mf][nf][half * 2], v1 = acc[mf][nf][half * 2 + 1];
                s += v0 * av[nf * 2] + v1 * av[nf * 2 + 1];
                d += v0 * dv[nf * 2] + v1 * dv[nf * 2 + 1];
            }
            s += __shfl_xor_sync(0xffffffffu, s, 1);
            s += __shfl_xor_sync(0xffffffffu, s, 2);
            d += __shfl_xor_sync(0xffffffffu, d, 1);
            d += __shfl_xor_sync(0xffffffffu, d, 2);
            if ((lane & 3) == 0 && gr < M) {
                gas[gr * 4 + wn] = s;
                gad[gr * 4 + wn] = d;
            }
        }
    }
}

// ---------------- mma.sync fp16 GEMM (MLP head) ----------------
// OUTMODE: 1 fp32 bias+sigmoid; 2 ext-fp16 bias (row = 2*Nlog)
template <int BN, int WM, int MF, int OUTMODE>
__global__ __launch_bounds__(256)
void k_gmma(const f16* __restrict__ A, const f16* __restrict__ B,
            const float* __restrict__ bias, void* __restrict__ Cout,
            int M, int Kext, int NB, int Nlog) {
    constexpr int LDA = 40;
    constexpr int LDB = BN + 8;
    constexpr int NB4 = BN * 32 / 2048;

    __shared__ f16 As[2][128 * LDA];
    __shared__ f16 Bs[2][32 * LDB];

    const int tid = threadIdx.x;
    const int warp = tid >> 5, lane = tid & 31;
    const int wm = warp % WM, wn = warp / WM;
    const int warpRow = wm * (MF * 16);
    const int warpCol = wn * 64;
    const int rowBase = blockIdx.y * 128;
    const int colBase = blockIdx.x * BN;

    float acc[MF][8][4];
#pragma unroll
    for (int i = 0; i < MF; i++)
#pragma unroll
        for (int j = 0; j < 8; j++)
#pragma unroll
            for (int q = 0; q < 4; q++) acc[i][j][q] = 0.f;

    const int nsteps = Kext / 32;
    int4 pa[2], pb[NB4];

#pragma unroll
    for (int i = 0; i < 2; i++) {
        int idx = tid + i * 256;
        int row = idx >> 2, q = idx & 3;
        int gr = rowBase + row;
        int4 v = (gr < M) ? *(const int4*)(A + (size_t)gr * Kext + q * 8)
                          : make_int4(0, 0, 0, 0);
        *(int4*)(&As[0][row * LDA + q * 8]) = v;
    }
#pragma unroll
    for (int i = 0; i < NB4; i++) {
        int idx = tid + i * 256;
        int k = idx / (BN / 8), q = idx % (BN / 8);
        int4 v = *(const int4*)(B + (size_t)k * NB + colBase + q * 8);
        *(int4*)(&Bs[0][k * LDB + q * 8]) = v;
    }
    __syncthreads();

    for (int s = 0; s < nsteps; ++s) {
        int buf = s & 1;
        bool more = (s + 1 < nsteps);
        int k0n = (s + 1) * 32;

        if (more) {
#pragma unroll
            for (int i = 0; i < 2; i++) {
                int idx = tid + i * 256;
                int row = idx >> 2, q = idx & 3;
                int gr = rowBase + row;
                pa[i] = (gr < M) ? *(const int4*)(A + (size_t)gr * Kext + k0n + q * 8)
                                 : make_int4(0, 0, 0, 0);
            }
#pragma unroll
            for (int i = 0; i < NB4; i++) {
                int idx = tid + i * 256;
                int k = idx / (BN / 8), q = idx % (BN / 8);
                pb[i] = *(const int4*)(B + (size_t)(k0n + k) * NB + colBase + q * 8);
            }
        }

        unsigned aB = smem_u32(&As[buf][0]);
        unsigned bB = smem_u32(&Bs[buf][0]);

#pragma unroll
        for (int ks = 0; ks < 32; ks += 16) {
            unsigned a[MF][4];
#pragma unroll
            for (int mf = 0; mf < MF; mf++) {
                int row = warpRow + mf * 16 + (lane & 15);
                int col = ks + ((lane & 16) ? 8 : 0);
                ldsm4(aB + (row * LDA + col) * 2, a[mf][0], a[mf][1], a[mf][2], a[mf][3]);
            }
            unsigned bb[8][2];
#pragma unroll
            for (int g = 0; g < 4; g++) {
                int kk = ks + (lane & 15);
                int nn = warpCol + g * 16 + ((lane & 16) ? 8 : 0);
                unsigned r0, r1, r2, r3;
                ldsm4t(bB + (kk * LDB + nn) * 2, r0, r1, r2, r3);
                bb[2 * g][0] = r0; bb[2 * g][1] = r1;
                bb[2 * g + 1][0] = r2; bb[2 * g + 1][1] = r3;
            }
#pragma unroll
            for (int mf = 0; mf < MF; mf++)
#pragma unroll
                for (int nf = 0; nf < 8; nf++)
                    mma16816(acc[mf][nf][0], acc[mf][nf][1], acc[mf][nf][2], acc[mf][nf][3],
                             a[mf][0], a[mf][1], a[mf][2], a[mf][3],
                             bb[nf][0], bb[nf][1]);
        }

        if (more) {
            int nb = buf ^ 1;
#pragma unroll
            for (int i = 0; i < 2; i++) {
                int idx = tid + i * 256;
                int row = idx >> 2, q = idx & 3;
                *(int4*)(&As[nb][row * LDA + q * 8]) = pa[i];
            }
#pragma unroll
            for (int i = 0; i < NB4; i++) {
                int idx = tid + i * 256;
                int k = idx / (BN / 8), q = idx % (BN / 8);
                *(int4*)(&Bs[nb][k * LDB + q * 8]) = pb[i];
            }
        }
        __syncthreads();
    }

#pragma unroll
    for (int mf = 0; mf < MF; mf++) {
#pragma unroll
        for (int nf = 0; nf < 8; nf++) {
            int gr0 = rowBase + warpRow + mf * 16 + (lane >> 2);
            int gc  = colBase + warpCol + nf * 8 + (lane & 3) * 2;
#pragma unroll
            for (int half = 0; half < 2; half++) {
                int gr = gr0 + half * 8;
                if (gr >= M) continue;
                float v0 = acc[mf][nf][half * 2 + 0];
                float v1 = acc[mf][nf][half * 2 + 1];
                if (OUTMODE == 1) {
                    float* C = (float*)Cout;
                    if (gc < Nlog)
                        C[(size_t)gr * Nlog + gc] = 1.f / (1.f + __expf(-(v0 + bias[gc])));
                    if (gc + 1 < Nlog)
                        C[(size_t)gr * Nlog + gc + 1] = 1.f / (1.f + __expf(-(v1 + bias[gc + 1])));
                } else {
                    f16* C = (f16*)Cout;
                    size_t base = (size_t)gr * (2 * Nlog);
                    float w0 = v0 + bias[gc], w1 = v1 + bias[gc + 1];
                    f16 h0, l0, h1, l1;
                    split_h(w0, h0, l0);
                    split_h(w1, h1, l1);
                    C[base + gc] = h0;     C[base + Nlog + gc] = l0;
                    C[base + gc + 1] = h1; C[base + Nlog + gc + 1] = l1;
                }
            }
        }
    }
}

// ---------------- launch ----------------
extern "C" void kernel_launch(void* const* d_in, const int* in_sizes, int n_in,
                              void* d_out, int out_size) {
    const float* x   = (const float*)d_in[0];
    const void*  ei  = d_in[1];
    const float* W1  = (const float*)d_in[2];
    const float* as1 = (const float*)d_in[3];
    const float* ad1 = (const float*)d_in[4];
    const float* b1  = (const float*)d_in[5];
    const float* W2  = (const float*)d_in[6];
    const float* as2 = (const float*)d_in[7];
    const float* ad2 = (const float*)d_in[8];
    const float* b2  = (const float*)d_in[9];
    const float* Wm1 = (const float*)d_in[10];
    const float* bm1 = (const float*)d_in[11];
    const float* Wm2 = (const float*)d_in[12];
    const float* bm2 = (const float*)d_in[13];
    float* out = (float*)d_out;

    void* cntp; cudaGetSymbolAddress(&cntp, g_cnt);
    f16 *ax, *aext, *midext, *b1e, *b2e, *b3e, *b4e;
    float *h1, *gas, *gad;
    cudaGetSymbolAddress((void**)&ax, g_ax);
    cudaGetSymbolAddress((void**)&aext, g_aext);
    cudaGetSymbolAddress((void**)&midext, g_midext);
    cudaGetSymbolAddress((void**)&h1, g_h1);
    cudaGetSymbolAddress((void**)&gas, g_as);
    cudaGetSymbolAddress((void**)&gad, g_ad);
    cudaGetSymbolAddress((void**)&b1e, g_b1e);
    cudaGetSymbolAddress((void**)&b2e, g_b2e);
    cudaGetSymbolAddress((void**)&b3e, g_b3e);
    cudaGetSymbolAddress((void**)&b4e, g_b4e);

    const int MB = (Nn + 127) / 128;  // 391
    const int G256_SMEM = 3 * (128 * 40 + 32 * 264) * (int)sizeof(f16);  // 81408
    cudaFuncSetAttribute(k_g256, cudaFuncAttributeMaxDynamicSharedMemorySize, G256_SMEM);

    // launch idx 3 = layer-1 GEMM (ncu capture target)
    k_convA<<<(Nn * 128 + 255) / 256, 256>>>(x, ax, Nn, 128);                    // 0
    k_convB<<<(128 * 256 + 255) / 256, 256>>>(W1, b1e, 128, 256, 256);           // 1
    k_convB<<<(256 * 256 + 255) / 256, 256>>>(W2, b2e, 256, 256, 256);           // 2
    k_g256<<<dim3(1, MB), 512, G256_SMEM>>>(ax, b1e, h1, Nn, 256,
                                            as1, ad1, gas, gad);                 // 3
    k_convB<<<(256 * 64 + 255) / 256, 256>>>(Wm1, b3e, 256, 64, 64);
    k_convB<<<(64 * 128 + 255) / 256, 256>>>(Wm2, b4e, 64, 121, 128);

    // --- CSR build ---
    k_detect<<<1, 256>>>((const long long*)ei);
    cudaMemsetAsync(cntp, 0, Nn * sizeof(int));
    k_hist<<<(ETOT + 255) / 256, 256>>>(ei);
    k_scan_block<<<49, 1024>>>();
    k_scan_bsum<<<1, 64>>>(49);
    k_scan_add<<<49, 1024>>>();
    cudaMemsetAsync(cntp, 0, Nn * sizeof(int));
    k_scatter<<<(ETOT + 255) / 256, 256>>>(ei);

    // --- layer 1 agg (attn fused into GEMM epilogue) ---
    k_agg3<<<Nn, 128>>>(h1, b1, aext);
    // --- layer 2 ---
    k_g256<<<dim3(1, MB), 512, G256_SMEM>>>(aext, b2e, h1, Nn, 512,
                                            as2, ad2, gas, gad);
    k_agg3<<<Nn, 128>>>(h1, b2, aext);
    // --- MLP head ---
    k_gmma<64, 8, 1, 2><<<dim3(1, MB), 256>>>(aext, b3e, bm1, midext, Nn, 512, 64, 64);
    k_gmma<128, 4, 2, 1><<<dim3(1, MB), 256>>>(midext, b4e, bm2, out, Nn, 128, 128, 121);
}

// round 12
// speedup vs baseline: 1.2963x; 1.2963x over previous
#include <cuda_runtime.h>
#include <cuda_bf16.h>
#include <cuda_fp16.h>
#include <cstdint>
#include <math.h>

#define Nn   50000
#define Ee   800000
#define ETOT 850000
#define HC   256
#define CH   128

typedef __nv_bfloat16 bf16;

// ---------------- static device scratch ----------------
__device__ __align__(16) bf16   g_ax[(size_t)Nn * 384];
__device__ __align__(16) bf16   g_aext[(size_t)Nn * 768];
__device__ __align__(16) bf16   g_midext[(size_t)Nn * 192];
__device__ __align__(16) __half g_h1[(size_t)Nn * HC];     // fp16 h (gather-only)
__device__ __align__(16) bf16   g_b1e[384 * 256];
__device__ __align__(16) bf16   g_b2e[768 * 256];
__device__ __align__(16) bf16   g_b3e[768 * 64];
__device__ __align__(16) bf16   g_b4e[192 * 128];
__device__ float g_as[Nn * 4];
__device__ float g_ad[Nn * 4];
__device__ int   g_cnt[Nn];
__device__ int   g_incl[Nn];
__device__ int   g_bsum[64];
__device__ int   g_rowptr[Nn + 1];
__device__ int   g_csrc[ETOT];
__device__ int   g_is64;

// ---------------- edge-index dtype detection ----------------
__global__ void k_detect(const long long* ei) {
    __shared__ int bad;
    if (threadIdx.x == 0) bad = 0;
    __syncthreads();
    long long v = ei[threadIdx.x];
    if (v < 0 || v >= Nn) atomicExch(&bad, 1);
    __syncthreads();
    if (threadIdx.x == 0) g_is64 = bad ? 0 : 1;
}

__device__ __forceinline__ int edge_at(const void* ei, int which, int i) {
    if (g_is64) return (int)((const long long*)ei)[(size_t)which * Ee + i];
    return ((const int*)ei)[(size_t)which * Ee + i];
}

// ---------------- CSR build ----------------
__global__ void k_hist(const void* ei) {
    int i = blockIdx.x * blockDim.x + threadIdx.x;
    if (i >= ETOT) return;
    int d = (i < Ee) ? edge_at(ei, 1, i) : (i - Ee);
    atomicAdd(&g_cnt[d], 1);
}

__global__ void k_scan_block() {
    __shared__ int sh[1024];
    int i = blockIdx.x * 1024 + threadIdx.x;
    int v = (i < Nn) ? g_cnt[i] : 0;
    sh[threadIdx.x] = v;
    __syncthreads();
    for (int off = 1; off < 1024; off <<= 1) {
        int t = (threadIdx.x >= off) ? sh[threadIdx.x - off] : 0;
        __syncthreads();
        sh[threadIdx.x] += t;
        __syncthreads();
    }
    if (i < Nn) g_incl[i] = sh[threadIdx.x];
    if (threadIdx.x == 1023) g_bsum[blockIdx.x] = sh[1023];
}

__global__ void k_scan_bsum(int nb) {
    __shared__ int sh[64];
    int v = (threadIdx.x < nb) ? g_bsum[threadIdx.x] : 0;
    sh[threadIdx.x] = v;
    __syncthreads();
    for (int off = 1; off < 64; off <<= 1) {
        int t = (threadIdx.x >= off) ? sh[threadIdx.x - off] : 0;
        __syncthreads();
        sh[threadIdx.x] += t;
        __syncthreads();
    }
    if (threadIdx.x < nb) g_bsum[threadIdx.x] = sh[threadIdx.x];
}

__global__ void k_scan_add() {
    int i = blockIdx.x * 1024 + threadIdx.x;
    if (i < Nn) {
        int add = blockIdx.x ? g_bsum[blockIdx.x - 1] : 0;
        g_rowptr[i + 1] = g_incl[i] + add;
        if (i == 0) g_rowptr[0] = 0;
    }
}

__global__ void k_scatter(const void* ei) {
    int i = blockIdx.x * blockDim.x + threadIdx.x;
    if (i >= ETOT) return;
    int s, d;
    if (i < Ee) { s = edge_at(ei, 0, i); d = edge_at(ei, 1, i); }
    else        { s = d = i - Ee; }
    int pos = g_rowptr[d] + atomicAdd(&g_cnt[d], 1);
    g_csrc[pos] = s;
}

// ---------------- split-bf16 conversions ----------------
__device__ __forceinline__ void split_bf(float v, bf16& hi, bf16& lo) {
    hi = __float2bfloat16(v);
    lo = __float2bfloat16(v - __bfloat162float(hi));
}

__global__ void k_convA(const float* __restrict__ X, bf16* __restrict__ out, int M, int K) {
    int idx = blockIdx.x * blockDim.x + threadIdx.x;
    if (idx >= M * K) return;
    int m = idx / K, k = idx % K;
    bf16 hi, lo;
    split_bf(X[idx], hi, lo);
    size_t base = (size_t)m * (3 * K);
    out[base + k] = hi;
    out[base + K + k] = lo;
    out[base + 2 * K + k] = hi;
}

__global__ void k_convB(const float* __restrict__ W, bf16* __restrict__ out,
                        int K, int Nsrc, int Nphys) {
    int idx = blockIdx.x * blockDim.x + threadIdx.x;
    if (idx >= K * Nphys) return;
    int k = idx / Nphys, n = idx % Nphys;
    float v = (n < Nsrc) ? W[k * Nsrc + n] : 0.f;
    bf16 hi, lo;
    split_bf(v, hi, lo);
    out[(size_t)k * Nphys + n] = hi;
    out[(size_t)(K + k) * Nphys + n] = hi;
    out[(size_t)(2 * K + k) * Nphys + n] = lo;
}

// ---------------- single-pass online-softmax aggregation (fp16 gather) ----------------
__global__ __launch_bounds__(128)
void k_agg3(const __half* __restrict__ h,
            const float* __restrict__ bias,
            bf16* __restrict__ outext) {
    int n = blockIdx.x;
    int tid = threadIdx.x;
    int w = tid >> 5, l = tid & 31;
    int beg = g_rowptr[n], end = g_rowptr[n + 1];
    float adv = g_ad[n * 4 + w];

    __shared__ int   s_src[CH];
    __shared__ float s_t[CH][4];

    float acc0 = 0.f, acc1 = 0.f, den = 0.f, m = -1e30f;

    for (int c0 = beg; c0 < end; c0 += CH) {
        int cnt = min(CH, end - c0);
        __syncthreads();
        for (int i = tid; i < cnt; i += 128) s_src[i] = g_csrc[c0 + i];
        __syncthreads();

        float cm = -1e30f;
        for (int i = l; i < cnt; i += 32) {
            float t = g_as[s_src[i] * 4 + w] + adv;
            t = (t > 0.f) ? t : 0.2f * t;
            s_t[i][w] = t;
            cm = fmaxf(cm, t);
        }
        for (int o = 16; o; o >>= 1) cm = fmaxf(cm, __shfl_xor_sync(0xffffffffu, cm, o));
        __syncwarp();

        float nm = fmaxf(m, cm);
        float sc = __expf(m - nm);
        acc0 *= sc; acc1 *= sc; den *= sc;
        m = nm;

#pragma unroll 4
        for (int e = 0; e < cnt; e++) {
            float wt = __expf(s_t[e][w] - m);
            den += wt;
            __half2 hv = *(const __half2*)(h + (size_t)s_src[e] * HC + w * 64 + 2 * l);
            float2 v = __half22float2(hv);
            acc0 += wt * v.x;
            acc1 += wt * v.y;
        }
    }

    float inv = 1.f / (den + 1e-16f);
    int c0 = w * 64 + 2 * l, c1 = c0 + 1;
    float v0 = fmaxf(acc0 * inv + bias[c0], 0.f);
    float v1 = fmaxf(acc1 * inv + bias[c1], 0.f);
    bf16 h0, l0, h1b, l1;
    split_bf(v0, h0, l0);
    split_bf(v1, h1b, l1);
    size_t base = (size_t)n * 768;
    outext[base + c0] = h0;  outext[base + 256 + c0] = l0;  outext[base + 512 + c0] = h0;
    outext[base + c1] = h1b; outext[base + 256 + c1] = l1;  outext[base + 512 + c1] = h1b;
}

// ---------------- mma helpers (bf16) ----------------
__device__ __forceinline__ unsigned smem_u32(const void* p) {
    return (unsigned)__cvta_generic_to_shared(p);
}
__device__ __forceinline__ void ldsm4(unsigned addr, unsigned& r0, unsigned& r1,
                                      unsigned& r2, unsigned& r3) {
    asm volatile("ldmatrix.sync.aligned.m8n8.x4.shared.b16 {%0,%1,%2,%3},[%4];"
                 : "=r"(r0), "=r"(r1), "=r"(r2), "=r"(r3) : "r"(addr));
}
__device__ __forceinline__ void ldsm4t(unsigned addr, unsigned& r0, unsigned& r1,
                                       unsigned& r2, unsigned& r3) {
    asm volatile("ldmatrix.sync.aligned.m8n8.x4.trans.shared.b16 {%0,%1,%2,%3},[%4];"
                 : "=r"(r0), "=r"(r1), "=r"(r2), "=r"(r3) : "r"(addr));
}
__device__ __forceinline__ void mma16816(float& c0, float& c1, float& c2, float& c3,
                                         unsigned a0, unsigned a1, unsigned a2, unsigned a3,
                                         unsigned b0, unsigned b1) {
    asm volatile("mma.sync.aligned.m16n8k16.row.col.f32.bf16.bf16.f32 "
                 "{%0,%1,%2,%3},{%4,%5,%6,%7},{%8,%9},{%0,%1,%2,%3};"
                 : "+f"(c0), "+f"(c1), "+f"(c2), "+f"(c3)
                 : "r"(a0), "r"(a1), "r"(a2), "r"(a3), "r"(b0), "r"(b1));
}
__device__ __forceinline__ void cp16(unsigned dst, const void* src) {
    asm volatile("cp.async.cg.shared.global [%0], [%1], 16;" :: "r"(dst), "l"(src));
}
__device__ __forceinline__ void cp_commit() {
    asm volatile("cp.async.commit_group;" ::: "memory");
}
__device__ __forceinline__ void cp_wait1() {
    asm volatile("cp.async.wait_group 1;" ::: "memory");
}

// ---------------- 128x256 3-stage cp.async bf16 GEMM + fused attention dots ----------------
// 512 threads, 16 warps: 4 along M x 4 along N, 32x64 per warp. fp16 C out.
__global__ __launch_bounds__(512)
void k_g256(const bf16* __restrict__ A, const bf16* __restrict__ B,
            __half* __restrict__ C, int M, int Kext,
            const float* __restrict__ asrc, const float* __restrict__ adst,
            float* __restrict__ gas, float* __restrict__ gad) {
    constexpr int LDA = 40;
    constexpr int LDB = 264;
    constexpr int ASZ = 128 * LDA;
    constexpr int BSZ = 32 * LDB;

    extern __shared__ bf16 sm[];
    bf16* As = sm;
    bf16* Bs = sm + 3 * ASZ;

    const int tid = threadIdx.x;
    const int warp = tid >> 5, lane = tid & 31;
    const int wm = warp & 3, wn = warp >> 2;
    const int warpRow = wm * 32;
    const int warpCol = wn * 64;
    const int rowBase = blockIdx.y * 128;

    float acc[2][8][4];
#pragma unroll
    for (int i = 0; i < 2; i++)
#pragma unroll
        for (int j = 0; j < 8; j++)
#pragma unroll
            for (int q = 0; q < 4; q++) acc[i][j][q] = 0.f;

    const int nsteps = Kext / 32;
    const int arow = tid >> 2, aq = tid & 3;

    auto load_stage = [&](int st, int k0) {
        unsigned abase = smem_u32(&As[st * ASZ]);
        unsigned bbase = smem_u32(&Bs[st * BSZ]);
        {
            int gr = min(rowBase + arow, M - 1);
            cp16(abase + (arow * LDA + aq * 8) * 2,
                 A + (size_t)gr * Kext + k0 + aq * 8);
        }
#pragma unroll
        for (int i = 0; i < 2; i++) {
            int idx = tid + i * 512;
            int k = idx >> 5, qb = idx & 31;
            cp16(bbase + (k * LDB + qb * 8) * 2,
                 B + (size_t)(k0 + k) * 256 + qb * 8);
        }
    };

    load_stage(0, 0);
    cp_commit();
    if (1 < nsteps) load_stage(1, 32);
    cp_commit();
    cp_wait1();
    __syncthreads();

    for (int s = 0; s < nsteps; ++s) {
        int buf = s % 3;
        unsigned aB = smem_u32(&As[buf * ASZ]);
        unsigned bB = smem_u32(&Bs[buf * BSZ]);

#pragma unroll
        for (int ks = 0; ks < 32; ks += 16) {
            unsigned a[2][4];
#pragma unroll
            for (int mf = 0; mf < 2; mf++) {
                int row = warpRow + mf * 16 + (lane & 15);
                int col = ks + ((lane & 16) ? 8 : 0);
                ldsm4(aB + (row * LDA + col) * 2, a[mf][0], a[mf][1], a[mf][2], a[mf][3]);
            }
            unsigned bb[8][2];
#pragma unroll
            for (int g = 0; g < 4; g++) {
                int kk = ks + (lane & 15);
                int nn = warpCol + g * 16 + ((lane & 16) ? 8 : 0);
                unsigned r0, r1, r2, r3;
                ldsm4t(bB + (kk * LDB + nn) * 2, r0, r1, r2, r3);
                bb[2 * g][0] = r0; bb[2 * g][1] = r1;
                bb[2 * g + 1][0] = r2; bb[2 * g + 1][1] = r3;
            }
#pragma unroll
            for (int mf = 0; mf < 2; mf++)
#pragma unroll
                for (int nf = 0; nf < 8; nf++)
                    mma16816(acc[mf][nf][0], acc[mf][nf][1], acc[mf][nf][2], acc[mf][nf][3],
                             a[mf][0], a[mf][1], a[mf][2], a[mf][3],
                             bb[nf][0], bb[nf][1]);
        }

        int nx = s + 2;
        if (nx < nsteps) load_stage(nx % 3, nx * 32);
        cp_commit();
        cp_wait1();
        __syncthreads();
    }

    // ---- epilogue: fp16 C stores ----
#pragma unroll
    for (int mf = 0; mf < 2; mf++) {
#pragma unroll
        for (int nf = 0; nf < 8; nf++) {
            int gr0 = rowBase + warpRow + mf * 16 + (lane >> 2);
            int gc  = warpCol + nf * 8 + (lane & 3) * 2;
#pragma unroll
            for (int half = 0; half < 2; half++) {
                int gr = gr0 + half * 8;
                if (gr >= M) continue;
                __half2 hv = __floats2half2_rn(acc[mf][nf][half * 2],
                                               acc[mf][nf][half * 2 + 1]);
                *(__half2*)(C + (size_t)gr * 256 + gc) = hv;
            }
        }
    }

    // ---- fused attention dot products (fp32 accs) ----
    float av[16], dv[16];
#pragma unroll
    for (int nf = 0; nf < 8; nf++) {
        int gc = warpCol + nf * 8 + (lane & 3) * 2;
        av[nf * 2 + 0] = asrc[gc];     av[nf * 2 + 1] = asrc[gc + 1];
        dv[nf * 2 + 0] = adst[gc];     dv[nf * 2 + 1] = adst[gc + 1];
    }
#pragma unroll
    for (int mf = 0; mf < 2; mf++) {
#pragma unroll
        for (int half = 0; half < 2; half++) {
            int gr = rowBase + warpRow + mf * 16 + (lane >> 2) + half * 8;
            float s = 0.f, d = 0.f;
#pragma unroll
            for (int nf = 0; nf < 8; nf++) {
                float v0 = acc[mf][nf][half * 2], v1 = acc[mf][nf][half * 2 + 1];
                s += v0 * av[nf * 2] + v1 * av[nf * 2 + 1];
                d += v0 * dv[nf * 2] + v1 * dv[nf * 2 + 1];
            }
            s += __shfl_xor_sync(0xffffffffu, s, 1);
            s += __shfl_xor_sync(0xffffffffu, s, 2);
            d += __shfl_xor_sync(0xffffffffu, d, 1);
            d += __shfl_xor_sync(0xffffffffu, d, 2);
            if ((lane & 3) == 0 && gr < M) {
                gas[gr * 4 + wn] = s;
                gad[gr * 4 + wn] = d;
            }
        }
    }
}

// ---------------- mma.sync bf16 GEMM (MLP head, proven) ----------------
template <int BN, int WM, int MF, int OUTMODE>
__global__ __launch_bounds__(256)
void k_gmma(const bf16* __restrict__ A, const bf16* __restrict__ B,
            const float* __restrict__ bias, void* __restrict__ Cout,
            int M, int Kext, int NB, int Nlog) {
    constexpr int LDA = 40;
    constexpr int LDB = BN + 8;
    constexpr int NB4 = BN * 32 / 2048;

    __shared__ bf16 As[2][128 * LDA];
    __shared__ bf16 Bs[2][32 * LDB];

    const int tid = threadIdx.x;
    const int warp = tid >> 5, lane = tid & 31;
    const int wm = warp % WM, wn = warp / WM;
    const int warpRow = wm * (MF * 16);
    const int warpCol = wn * 64;
    const int rowBase = blockIdx.y * 128;
    const int colBase = blockIdx.x * BN;

    float acc[MF][8][4];
#pragma unroll
    for (int i = 0; i < MF; i++)
#pragma unroll
        for (int j = 0; j < 8; j++)
#pragma unroll
            for (int q = 0; q < 4; q++) acc[i][j][q] = 0.f;

    const int nsteps = Kext / 32;
    int4 pa[2], pb[NB4];

#pragma unroll
    for (int i = 0; i < 2; i++) {
        int idx = tid + i * 256;
        int row = idx >> 2, q = idx & 3;
        int gr = rowBase + row;
        int4 v = (gr < M) ? *(const int4*)(A + (size_t)gr * Kext + q * 8)
                          : make_int4(0, 0, 0, 0);
        *(int4*)(&As[0][row * LDA + q * 8]) = v;
    }
#pragma unroll
    for (int i = 0; i < NB4; i++) {
        int idx = tid + i * 256;
        int k = idx / (BN / 8), q = idx % (BN / 8);
        int4 v = *(const int4*)(B + (size_t)k * NB + colBase + q * 8);
        *(int4*)(&Bs[0][k * LDB + q * 8]) = v;
    }
    __syncthreads();

    for (int s = 0; s < nsteps; ++s) {
        int buf = s & 1;
        bool more = (s + 1 < nsteps);
        int k0n = (s + 1) * 32;

        if (more) {
#pragma unroll
            for (int i = 0; i < 2; i++) {
                int idx = tid + i * 256;
                int row = idx >> 2, q = idx & 3;
                int gr = rowBase + row;
                pa[i] = (gr < M) ? *(const int4*)(A + (size_t)gr * Kext + k0n + q * 8)
                                 : make_int4(0, 0, 0, 0);
            }
#pragma unroll
            for (int i = 0; i < NB4; i++) {
                int idx = tid + i * 256;
                int k = idx / (BN / 8), q = idx % (BN / 8);
                pb[i] = *(const int4*)(B + (size_t)(k0n + k) * NB + colBase + q * 8);
            }
        }

        unsigned aB = smem_u32(&As[buf][0]);
        unsigned bB = smem_u32(&Bs[buf][0]);

#pragma unroll
        for (int ks = 0; ks < 32; ks += 16) {
            unsigned a[MF][4];
#pragma unroll
            for (int mf = 0; mf < MF; mf++) {
                int row = warpRow + mf * 16 + (lane & 15);
                int col = ks + ((lane & 16) ? 8 : 0);
                ldsm4(aB + (row * LDA + col) * 2, a[mf][0], a[mf][1], a[mf][2], a[mf][3]);
            }
            unsigned bb[8][2];
#pragma unroll
            for (int g = 0; g < 4; g++) {
                int kk = ks + (lane & 15);
                int nn = warpCol + g * 16 + ((lane & 16) ? 8 : 0);
                unsigned r0, r1, r2, r3;
                ldsm4t(bB + (kk * LDB + nn) * 2, r0, r1, r2, r3);
                bb[2 * g][0] = r0; bb[2 * g][1] = r1;
                bb[2 * g + 1][0] = r2; bb[2 * g + 1][1] = r3;
            }
#pragma unroll
            for (int mf = 0; mf < MF; mf++)
#pragma unroll
                for (int nf = 0; nf < 8; nf++)
                    mma16816(acc[mf][nf][0], acc[mf][nf][1], acc[mf][nf][2], acc[mf][nf][3],
                             a[mf][0], a[mf][1], a[mf][2], a[mf][3],
                             bb[nf][0], bb[nf][1]);
        }

        if (more) {
            int nb = buf ^ 1;
#pragma unroll
            for (int i = 0; i < 2; i++) {
                int idx = tid + i * 256;
                int row = idx >> 2, q = idx & 3;
                *(int4*)(&As[nb][row * LDA + q * 8]) = pa[i];
            }
#pragma unroll
            for (int i = 0; i < NB4; i++) {
                int idx = tid + i * 256;
                int k = idx / (BN / 8), q = idx % (BN / 8);
                *(int4*)(&Bs[nb][k * LDB + q * 8]) = pb[i];
            }
        }
        __syncthreads();
    }

#pragma unroll
    for (int mf = 0; mf < MF; mf++) {
#pragma unroll
        for (int nf = 0; nf < 8; nf++) {
            int gr0 = rowBase + warpRow + mf * 16 + (lane >> 2);
            int gc  = colBase + warpCol + nf * 8 + (lane & 3) * 2;
#pragma unroll
            for (int half = 0; half < 2; half++) {
                int gr = gr0 + half * 8;
                if (gr >= M) continue;
                float v0 = acc[mf][nf][half * 2 + 0];
                float v1 = acc[mf][nf][half * 2 + 1];
                if (OUTMODE == 1) {
                    float* C = (float*)Cout;
                    if (gc < Nlog)
                        C[(size_t)gr * Nlog + gc] = 1.f / (1.f + __expf(-(v0 + bias[gc])));
                    if (gc + 1 < Nlog)
                        C[(size_t)gr * Nlog + gc + 1] = 1.f / (1.f + __expf(-(v1 + bias[gc + 1])));
                } else {
                    bf16* C = (bf16*)Cout;
                    size_t base = (size_t)gr * (3 * Nlog);
                    float w0 = v0 + bias[gc], w1 = v1 + bias[gc + 1];
                    bf16 h0, l0, h1, l1;
                    split_bf(w0, h0, l0);
                    split_bf(w1, h1, l1);
                    C[base + gc] = h0; C[base + Nlog + gc] = l0; C[base + 2 * Nlog + gc] = h0;
                    C[base + gc + 1] = h1; C[base + Nlog + gc + 1] = l1; C[base + 2 * Nlog + gc + 1] = h1;
                }
            }
        }
    }
}

// ---------------- launch ----------------
extern "C" void kernel_launch(void* const* d_in, const int* in_sizes, int n_in,
                              void* d_out, int out_size) {
    const float* x   = (const float*)d_in[0];
    const void*  ei  = d_in[1];
    const float* W1  = (const float*)d_in[2];
    const float* as1 = (const float*)d_in[3];
    const float* ad1 = (const float*)d_in[4];
    const float* b1  = (const float*)d_in[5];
    const float* W2  = (const float*)d_in[6];
    const float* as2 = (const float*)d_in[7];
    const float* ad2 = (const float*)d_in[8];
    const float* b2  = (const float*)d_in[9];
    const float* Wm1 = (const float*)d_in[10];
    const float* bm1 = (const float*)d_in[11];
    const float* Wm2 = (const float*)d_in[12];
    const float* bm2 = (const float*)d_in[13];
    float* out = (float*)d_out;

    void* cntp; cudaGetSymbolAddress(&cntp, g_cnt);
    bf16 *ax, *aext, *midext, *b1e, *b2e, *b3e, *b4e;
    __half* h1;
    float *gas, *gad;
    cudaGetSymbolAddress((void**)&ax, g_ax);
    cudaGetSymbolAddress((void**)&aext, g_aext);
    cudaGetSymbolAddress((void**)&midext, g_midext);
    cudaGetSymbolAddress((void**)&h1, g_h1);
    cudaGetSymbolAddress((void**)&gas, g_as);
    cudaGetSymbolAddress((void**)&gad, g_ad);
    cudaGetSymbolAddress((void**)&b1e, g_b1e);
    cudaGetSymbolAddress((void**)&b2e, g_b2e);
    cudaGetSymbolAddress((void**)&b3e, g_b3e);
    cudaGetSymbolAddress((void**)&b4e, g_b4e);

    const int MB = (Nn + 127) / 128;  // 391
    const int G256_SMEM = 3 * (128 * 40 + 32 * 264) * (int)sizeof(bf16);  // 81408
    cudaFuncSetAttribute(k_g256, cudaFuncAttributeMaxDynamicSharedMemorySize, G256_SMEM);

    // launch idx 3 = layer-1 GEMM (ncu capture target)
    k_convA<<<(Nn * 128 + 255) / 256, 256>>>(x, ax, Nn, 128);                    // 0
    k_convB<<<(128 * 256 + 255) / 256, 256>>>(W1, b1e, 128, 256, 256);           // 1
    k_convB<<<(256 * 256 + 255) / 256, 256>>>(W2, b2e, 256, 256, 256);           // 2
    k_g256<<<dim3(1, MB), 512, G256_SMEM>>>(ax, b1e, h1, Nn, 384,
                                            as1, ad1, gas, gad);                 // 3
    k_convB<<<(256 * 64 + 255) / 256, 256>>>(Wm1, b3e, 256, 64, 64);
    k_convB<<<(64 * 128 + 255) / 256, 256>>>(Wm2, b4e, 64, 121, 128);

    // --- CSR build ---
    k_detect<<<1, 256>>>((const long long*)ei);
    cudaMemsetAsync(cntp, 0, Nn * sizeof(int));
    k_hist<<<(ETOT + 255) / 256, 256>>>(ei);
    k_scan_block<<<49, 1024>>>();
    k_scan_bsum<<<1, 64>>>(49);
    k_scan_add<<<49, 1024>>>();
    cudaMemsetAsync(cntp, 0, Nn * sizeof(int));
    k_scatter<<<(ETOT + 255) / 256, 256>>>(ei);

    // --- layer 1 agg (attn fused into GEMM epilogue) ---
    k_agg3<<<Nn, 128>>>(h1, b1, aext);
    // --- layer 2 ---
    k_g256<<<dim3(1, MB), 512, G256_SMEM>>>(aext, b2e, h1, Nn, 768,
                                            as2, ad2, gas, gad);
    k_agg3<<<Nn, 128>>>(h1, b2, aext);
    // --- MLP head ---
    k_gmma<64, 8, 1, 2><<<dim3(1, MB), 256>>>(aext, b3e, bm1, midext, Nn, 768, 64, 64);
    k_gmma<128, 4, 2, 1><<<dim3(1, MB), 256>>>(midext, b4e, bm2, out, Nn, 192, 128, 121);
}

// round 13
// speedup vs baseline: 1.4074x; 1.0857x over previous
#include <cuda_runtime.h>
#include <cuda_bf16.h>
#include <cuda_fp16.h>
#include <cstdint>
#include <math.h>

#define Nn   50000
#define Ee   800000
#define ETOT 850000
#define HC   256
#define CH   128

typedef __nv_bfloat16 bf16;

// ---------------- static device scratch ----------------
__device__ __align__(16) bf16   g_ax[(size_t)Nn * 384];
__device__ __align__(16) bf16   g_aext[(size_t)Nn * 768];
__device__ __align__(16) __half g_h1[(size_t)Nn * HC];     // fp16 h (gather-only)
__device__ __align__(16) bf16   g_b1e[384 * 256];
__device__ __align__(16) bf16   g_b2e[768 * 256];
__device__ __align__(16) bf16   g_bWc[768 * 128];          // fused MLP weight ext
__device__ float g_bc[128];                                 // fused MLP bias
__device__ float g_as[Nn * 4];
__device__ float g_ad[Nn * 4];
__device__ int   g_cnt[Nn];
__device__ int   g_incl[Nn];
__device__ int   g_bsum[64];
__device__ int   g_rowptr[Nn + 1];
__device__ int   g_csrc[ETOT];
__device__ int   g_is64;

// ---------------- edge-index dtype detection ----------------
__global__ void k_detect(const long long* ei) {
    __shared__ int bad;
    if (threadIdx.x == 0) bad = 0;
    __syncthreads();
    long long v = ei[threadIdx.x];
    if (v < 0 || v >= Nn) atomicExch(&bad, 1);
    __syncthreads();
    if (threadIdx.x == 0) g_is64 = bad ? 0 : 1;
}

__device__ __forceinline__ int edge_at(const void* ei, int which, int i) {
    if (g_is64) return (int)((const long long*)ei)[(size_t)which * Ee + i];
    return ((const int*)ei)[(size_t)which * Ee + i];
}

// ---------------- CSR build ----------------
__global__ void k_hist(const void* ei) {
    int i = blockIdx.x * blockDim.x + threadIdx.x;
    if (i >= ETOT) return;
    int d = (i < Ee) ? edge_at(ei, 1, i) : (i - Ee);
    atomicAdd(&g_cnt[d], 1);
}

__global__ void k_scan_block() {
    __shared__ int sh[1024];
    int i = blockIdx.x * 1024 + threadIdx.x;
    int v = (i < Nn) ? g_cnt[i] : 0;
    sh[threadIdx.x] = v;
    __syncthreads();
    for (int off = 1; off < 1024; off <<= 1) {
        int t = (threadIdx.x >= off) ? sh[threadIdx.x - off] : 0;
        __syncthreads();
        sh[threadIdx.x] += t;
        __syncthreads();
    }
    if (i < Nn) g_incl[i] = sh[threadIdx.x];
    if (threadIdx.x == 1023) g_bsum[blockIdx.x] = sh[1023];
}

__global__ void k_scan_bsum(int nb) {
    __shared__ int sh[64];
    int v = (threadIdx.x < nb) ? g_bsum[threadIdx.x] : 0;
    sh[threadIdx.x] = v;
    __syncthreads();
    for (int off = 1; off < 64; off <<= 1) {
        int t = (threadIdx.x >= off) ? sh[threadIdx.x - off] : 0;
        __syncthreads();
        sh[threadIdx.x] += t;
        __syncthreads();
    }
    if (threadIdx.x < nb) g_bsum[threadIdx.x] = sh[threadIdx.x];
}

__global__ void k_scan_add() {
    int i = blockIdx.x * 1024 + threadIdx.x;
    if (i < Nn) {
        int add = blockIdx.x ? g_bsum[blockIdx.x - 1] : 0;
        g_rowptr[i + 1] = g_incl[i] + add;
        if (i == 0) g_rowptr[0] = 0;
    }
}

__global__ void k_scatter(const void* ei) {
    int i = blockIdx.x * blockDim.x + threadIdx.x;
    if (i >= ETOT) return;
    int s, d;
    if (i < Ee) { s = edge_at(ei, 0, i); d = edge_at(ei, 1, i); }
    else        { s = d = i - Ee; }
    int pos = g_rowptr[d] + atomicAdd(&g_cnt[d], 1);
    g_csrc[pos] = s;
}

// ---------------- split-bf16 conversions ----------------
__device__ __forceinline__ void split_bf(float v, bf16& hi, bf16& lo) {
    hi = __float2bfloat16(v);
    lo = __float2bfloat16(v - __bfloat162float(hi));
}

__global__ void k_convA(const float* __restrict__ X, bf16* __restrict__ out, int M, int K) {
    int idx = blockIdx.x * blockDim.x + threadIdx.x;
    if (idx >= M * K) return;
    int m = idx / K, k = idx % K;
    bf16 hi, lo;
    split_bf(X[idx], hi, lo);
    size_t base = (size_t)m * (3 * K);
    out[base + k] = hi;
    out[base + K + k] = lo;
    out[base + 2 * K + k] = hi;
}

__global__ void k_convB(const float* __restrict__ W, bf16* __restrict__ out,
                        int K, int Nsrc, int Nphys) {
    int idx = blockIdx.x * blockDim.x + threadIdx.x;
    if (idx >= K * Nphys) return;
    int k = idx / Nphys, n = idx % Nphys;
    float v = (n < Nsrc) ? W[k * Nsrc + n] : 0.f;
    bf16 hi, lo;
    split_bf(v, hi, lo);
    out[(size_t)k * Nphys + n] = hi;
    out[(size_t)(K + k) * Nphys + n] = hi;
    out[(size_t)(2 * K + k) * Nphys + n] = lo;
}

// ---------------- fused MLP weight precompute: Wc = Wm1@Wm2, bc = bm1@Wm2 + bm2 ----------------
// Wm1: [256,64], Wm2: [64,121]. Output ext layout [3*256 rows][128 cols].
__global__ void k_fuse(const float* __restrict__ Wm1, const float* __restrict__ bm1,
                       const float* __restrict__ Wm2, const float* __restrict__ bm2,
                       bf16* __restrict__ oute, float* __restrict__ bc) {
    int idx = blockIdx.x * blockDim.x + threadIdx.x;
    if (idx >= 256 * 128) return;
    int k = idx >> 7, n = idx & 127;
    float v = 0.f;
    if (n < 121) {
#pragma unroll 8
        for (int j = 0; j < 64; j++) v += Wm1[k * 64 + j] * Wm2[j * 121 + n];
    }
    bf16 hi, lo;
    split_bf(v, hi, lo);
    oute[(size_t)k * 128 + n] = hi;
    oute[(size_t)(256 + k) * 128 + n] = hi;
    oute[(size_t)(512 + k) * 128 + n] = lo;
    if (k == 0) {
        float b = 0.f;
        if (n < 121) {
#pragma unroll 8
            for (int j = 0; j < 64; j++) b += bm1[j] * Wm2[j * 121 + n];
            b += bm2[n];
        }
        bc[n] = b;
    }
}

// ---------------- single-pass online-softmax aggregation (fp16 gather) ----------------
__global__ __launch_bounds__(128)
void k_agg3(const __half* __restrict__ h,
            const float* __restrict__ bias,
            bf16* __restrict__ outext) {
    int n = blockIdx.x;
    int tid = threadIdx.x;
    int w = tid >> 5, l = tid & 31;
    int beg = g_rowptr[n], end = g_rowptr[n + 1];
    float adv = g_ad[n * 4 + w];

    __shared__ int   s_src[CH];
    __shared__ float s_t[CH][4];

    float acc0 = 0.f, acc1 = 0.f, den = 0.f, m = -1e30f;

    for (int c0 = beg; c0 < end; c0 += CH) {
        int cnt = min(CH, end - c0);
        __syncthreads();
        for (int i = tid; i < cnt; i += 128) s_src[i] = g_csrc[c0 + i];
        __syncthreads();

        float cm = -1e30f;
        for (int i = l; i < cnt; i += 32) {
            float t = g_as[s_src[i] * 4 + w] + adv;
            t = (t > 0.f) ? t : 0.2f * t;
            s_t[i][w] = t;
            cm = fmaxf(cm, t);
        }
        for (int o = 16; o; o >>= 1) cm = fmaxf(cm, __shfl_xor_sync(0xffffffffu, cm, o));
        __syncwarp();

        float nm = fmaxf(m, cm);
        float sc = __expf(m - nm);
        acc0 *= sc; acc1 *= sc; den *= sc;
        m = nm;

#pragma unroll 4
        for (int e = 0; e < cnt; e++) {
            float wt = __expf(s_t[e][w] - m);
            den += wt;
            __half2 hv = *(const __half2*)(h + (size_t)s_src[e] * HC + w * 64 + 2 * l);
            float2 v = __half22float2(hv);
            acc0 += wt * v.x;
            acc1 += wt * v.y;
        }
    }

    float inv = 1.f / (den + 1e-16f);
    int c0 = w * 64 + 2 * l, c1 = c0 + 1;
    float v0 = fmaxf(acc0 * inv + bias[c0], 0.f);
    float v1 = fmaxf(acc1 * inv + bias[c1], 0.f);
    bf16 h0, l0, h1b, l1;
    split_bf(v0, h0, l0);
    split_bf(v1, h1b, l1);
    size_t base = (size_t)n * 768;
    outext[base + c0] = h0;  outext[base + 256 + c0] = l0;  outext[base + 512 + c0] = h0;
    outext[base + c1] = h1b; outext[base + 256 + c1] = l1;  outext[base + 512 + c1] = h1b;
}

// ---------------- mma helpers (bf16) ----------------
__device__ __forceinline__ unsigned smem_u32(const void* p) {
    return (unsigned)__cvta_generic_to_shared(p);
}
__device__ __forceinline__ void ldsm4(unsigned addr, unsigned& r0, unsigned& r1,
                                      unsigned& r2, unsigned& r3) {
    asm volatile("ldmatrix.sync.aligned.m8n8.x4.shared.b16 {%0,%1,%2,%3},[%4];"
                 : "=r"(r0), "=r"(r1), "=r"(r2), "=r"(r3) : "r"(addr));
}
__device__ __forceinline__ void ldsm4t(unsigned addr, unsigned& r0, unsigned& r1,
                                       unsigned& r2, unsigned& r3) {
    asm volatile("ldmatrix.sync.aligned.m8n8.x4.trans.shared.b16 {%0,%1,%2,%3},[%4];"
                 : "=r"(r0), "=r"(r1), "=r"(r2), "=r"(r3) : "r"(addr));
}
__device__ __forceinline__ void mma16816(float& c0, float& c1, float& c2, float& c3,
                                         unsigned a0, unsigned a1, unsigned a2, unsigned a3,
                                         unsigned b0, unsigned b1) {
    asm volatile("mma.sync.aligned.m16n8k16.row.col.f32.bf16.bf16.f32 "
                 "{%0,%1,%2,%3},{%4,%5,%6,%7},{%8,%9},{%0,%1,%2,%3};"
                 : "+f"(c0), "+f"(c1), "+f"(c2), "+f"(c3)
                 : "r"(a0), "r"(a1), "r"(a2), "r"(a3), "r"(b0), "r"(b1));
}
__device__ __forceinline__ void cp16(unsigned dst, const void* src) {
    asm volatile("cp.async.cg.shared.global [%0], [%1], 16;" :: "r"(dst), "l"(src));
}
__device__ __forceinline__ void cp_commit() {
    asm volatile("cp.async.commit_group;" ::: "memory");
}
__device__ __forceinline__ void cp_wait1() {
    asm volatile("cp.async.wait_group 1;" ::: "memory");
}

// ---------------- 128x256 3-stage cp.async bf16 GEMM + fused attention dots ----------------
// 512 threads, 16 warps: 4 along M x 4 along N, 32x64 per warp. fp16 C out.
__global__ __launch_bounds__(512)
void k_g256(const bf16* __restrict__ A, const bf16* __restrict__ B,
            __half* __restrict__ C, int M, int Kext,
            const float* __restrict__ asrc, const float* __restrict__ adst,
            float* __restrict__ gas, float* __restrict__ gad) {
    constexpr int LDA = 40;
    constexpr int LDB = 264;
    constexpr int ASZ = 128 * LDA;
    constexpr int BSZ = 32 * LDB;

    extern __shared__ bf16 sm[];
    bf16* As = sm;
    bf16* Bs = sm + 3 * ASZ;

    const int tid = threadIdx.x;
    const int warp = tid >> 5, lane = tid & 31;
    const int wm = warp & 3, wn = warp >> 2;
    const int warpRow = wm * 32;
    const int warpCol = wn * 64;
    const int rowBase = blockIdx.y * 128;

    float acc[2][8][4];
#pragma unroll
    for (int i = 0; i < 2; i++)
#pragma unroll
        for (int j = 0; j < 8; j++)
#pragma unroll
            for (int q = 0; q < 4; q++) acc[i][j][q] = 0.f;

    const int nsteps = Kext / 32;
    const int arow = tid >> 2, aq = tid & 3;

    auto load_stage = [&](int st, int k0) {
        unsigned abase = smem_u32(&As[st * ASZ]);
        unsigned bbase = smem_u32(&Bs[st * BSZ]);
        {
            int gr = min(rowBase + arow, M - 1);
            cp16(abase + (arow * LDA + aq * 8) * 2,
                 A + (size_t)gr * Kext + k0 + aq * 8);
        }
#pragma unroll
        for (int i = 0; i < 2; i++) {
            int idx = tid + i * 512;
            int k = idx >> 5, qb = idx & 31;
            cp16(bbase + (k * LDB + qb * 8) * 2,
                 B + (size_t)(k0 + k) * 256 + qb * 8);
        }
    };

    load_stage(0, 0);
    cp_commit();
    if (1 < nsteps) load_stage(1, 32);
    cp_commit();
    cp_wait1();
    __syncthreads();

    for (int s = 0; s < nsteps; ++s) {
        int buf = s % 3;
        unsigned aB = smem_u32(&As[buf * ASZ]);
        unsigned bB = smem_u32(&Bs[buf * BSZ]);

#pragma unroll
        for (int ks = 0; ks < 32; ks += 16) {
            unsigned a[2][4];
#pragma unroll
            for (int mf = 0; mf < 2; mf++) {
                int row = warpRow + mf * 16 + (lane & 15);
                int col = ks + ((lane & 16) ? 8 : 0);
                ldsm4(aB + (row * LDA + col) * 2, a[mf][0], a[mf][1], a[mf][2], a[mf][3]);
            }
            unsigned bb[8][2];
#pragma unroll
            for (int g = 0; g < 4; g++) {
                int kk = ks + (lane & 15);
                int nn = warpCol + g * 16 + ((lane & 16) ? 8 : 0);
                unsigned r0, r1, r2, r3;
                ldsm4t(bB + (kk * LDB + nn) * 2, r0, r1, r2, r3);
                bb[2 * g][0] = r0; bb[2 * g][1] = r1;
                bb[2 * g + 1][0] = r2; bb[2 * g + 1][1] = r3;
            }
#pragma unroll
            for (int mf = 0; mf < 2; mf++)
#pragma unroll
                for (int nf = 0; nf < 8; nf++)
                    mma16816(acc[mf][nf][0], acc[mf][nf][1], acc[mf][nf][2], acc[mf][nf][3],
                             a[mf][0], a[mf][1], a[mf][2], a[mf][3],
                             bb[nf][0], bb[nf][1]);
        }

        int nx = s + 2;
        if (nx < nsteps) load_stage(nx % 3, nx * 32);
        cp_commit();
        cp_wait1();
        __syncthreads();
    }

    // ---- epilogue: fp16 C stores ----
#pragma unroll
    for (int mf = 0; mf < 2; mf++) {
#pragma unroll
        for (int nf = 0; nf < 8; nf++) {
            int gr0 = rowBase + warpRow + mf * 16 + (lane >> 2);
            int gc  = warpCol + nf * 8 + (lane & 3) * 2;
#pragma unroll
            for (int half = 0; half < 2; half++) {
                int gr = gr0 + half * 8;
                if (gr >= M) continue;
                __half2 hv = __floats2half2_rn(acc[mf][nf][half * 2],
                                               acc[mf][nf][half * 2 + 1]);
                *(__half2*)(C + (size_t)gr * 256 + gc) = hv;
            }
        }
    }

    // ---- fused attention dot products ----
    float av[16], dv[16];
#pragma unroll
    for (int nf = 0; nf < 8; nf++) {
        int gc = warpCol + nf * 8 + (lane & 3) * 2;
        av[nf * 2 + 0] = asrc[gc];     av[nf * 2 + 1] = asrc[gc + 1];
        dv[nf * 2 + 0] = adst[gc];     dv[nf * 2 + 1] = adst[gc + 1];
    }
#pragma unroll
    for (int mf = 0; mf < 2; mf++) {
#pragma unroll
        for (int half = 0; half < 2; half++) {
            int gr = rowBase + warpRow + mf * 16 + (lane >> 2) + half * 8;
            float s = 0.f, d = 0.f;
#pragma unroll
            for (int nf = 0; nf < 8; nf++) {
                float v0 = acc[mf][nf][half * 2], v1 = acc[mf][nf][half * 2 + 1];
                s += v0 * av[nf * 2] + v1 * av[nf * 2 + 1];
                d += v0 * dv[nf * 2] + v1 * dv[nf * 2 + 1];
            }
            s += __shfl_xor_sync(0xffffffffu, s, 1);
            s += __shfl_xor_sync(0xffffffffu, s, 2);
            d += __shfl_xor_sync(0xffffffffu, d, 1);
            d += __shfl_xor_sync(0xffffffffu, d, 2);
            if ((lane & 3) == 0 && gr < M) {
                gas[gr * 4 + wn] = s;
                gad[gr * 4 + wn] = d;
            }
        }
    }
}

// ---------------- mma.sync bf16 GEMM (final fused MLP, sigmoid out) ----------------
template <int BN, int WM, int MF>
__global__ __launch_bounds__(256)
void k_gmma(const bf16* __restrict__ A, const bf16* __restrict__ B,
            const float* __restrict__ bias, float* __restrict__ C,
            int M, int Kext, int NB, int Nlog) {
    constexpr int LDA = 40;
    constexpr int LDB = BN + 8;
    constexpr int NB4 = BN * 32 / 2048;

    __shared__ bf16 As[2][128 * LDA];
    __shared__ bf16 Bs[2][32 * LDB];

    const int tid = threadIdx.x;
    const int warp = tid >> 5, lane = tid & 31;
    const int wm = warp % WM, wn = warp / WM;
    const int warpRow = wm * (MF * 16);
    const int warpCol = wn * 64;
    const int rowBase = blockIdx.y * 128;
    const int colBase = blockIdx.x * BN;

    float acc[MF][8][4];
#pragma unroll
    for (int i = 0; i < MF; i++)
#pragma unroll
        for (int j = 0; j < 8; j++)
#pragma unroll
            for (int q = 0; q < 4; q++) acc[i][j][q] = 0.f;

    const int nsteps = Kext / 32;
    int4 pa[2], pb[NB4];

#pragma unroll
    for (int i = 0; i < 2; i++) {
        int idx = tid + i * 256;
        int row = idx >> 2, q = idx & 3;
        int gr = rowBase + row;
        int4 v = (gr < M) ? *(const int4*)(A + (size_t)gr * Kext + q * 8)
                          : make_int4(0, 0, 0, 0);
        *(int4*)(&As[0][row * LDA + q * 8]) = v;
    }
#pragma unroll
    for (int i = 0; i < NB4; i++) {
        int idx = tid + i * 256;
        int k = idx / (BN / 8), q = idx % (BN / 8);
        int4 v = *(const int4*)(B + (size_t)k * NB + colBase + q * 8);
        *(int4*)(&Bs[0][k * LDB + q * 8]) = v;
    }
    __syncthreads();

    for (int s = 0; s < nsteps; ++s) {
        int buf = s & 1;
        bool more = (s + 1 < nsteps);
        int k0n = (s + 1) * 32;

        if (more) {
#pragma unroll
            for (int i = 0; i < 2; i++) {
                int idx = tid + i * 256;
                int row = idx >> 2, q = idx & 3;
                int gr = rowBase + row;
                pa[i] = (gr < M) ? *(const int4*)(A + (size_t)gr * Kext + k0n + q * 8)
                                 : make_int4(0, 0, 0, 0);
            }
#pragma unroll
            for (int i = 0; i < NB4; i++) {
                int idx = tid + i * 256;
                int k = idx / (BN / 8), q = idx % (BN / 8);
                pb[i] = *(const int4*)(B + (size_t)(k0n + k) * NB + colBase + q * 8);
            }
        }

        unsigned aB = smem_u32(&As[buf][0]);
        unsigned bB = smem_u32(&Bs[buf][0]);

#pragma unroll
        for (int ks = 0; ks < 32; ks += 16) {
            unsigned a[MF][4];
#pragma unroll
            for (int mf = 0; mf < MF; mf++) {
                int row = warpRow + mf * 16 + (lane & 15);
                int col = ks + ((lane & 16) ? 8 : 0);
                ldsm4(aB + (row * LDA + col) * 2, a[mf][0], a[mf][1], a[mf][2], a[mf][3]);
            }
            unsigned bb[8][2];
#pragma unroll
            for (int g = 0; g < 4; g++) {
                int kk = ks + (lane & 15);
                int nn = warpCol + g * 16 + ((lane & 16) ? 8 : 0);
                unsigned r0, r1, r2, r3;
                ldsm4t(bB + (kk * LDB + nn) * 2, r0, r1, r2, r3);
                bb[2 * g][0] = r0; bb[2 * g][1] = r1;
                bb[2 * g + 1][0] = r2; bb[2 * g + 1][1] = r3;
            }
#pragma unroll
            for (int mf = 0; mf < MF; mf++)
#pragma unroll
                for (int nf = 0; nf < 8; nf++)
                    mma16816(acc[mf][nf][0], acc[mf][nf][1], acc[mf][nf][2], acc[mf][nf][3],
                             a[mf][0], a[mf][1], a[mf][2], a[mf][3],
                             bb[nf][0], bb[nf][1]);
        }

        if (more) {
            int nb = buf ^ 1;
#pragma unroll
            for (int i = 0; i < 2; i++) {
                int idx = tid + i * 256;
                int row = idx >> 2, q = idx & 3;
                *(int4*)(&As[nb][row * LDA + q * 8]) = pa[i];
            }
#pragma unroll
            for (int i = 0; i < NB4; i++) {
                int idx = tid + i * 256;
                int k = idx / (BN / 8), q = idx % (BN / 8);
                *(int4*)(&Bs[nb][k * LDB + q * 8]) = pb[i];
            }
        }
        __syncthreads();
    }

#pragma unroll
    for (int mf = 0; mf < MF; mf++) {
#pragma unroll
        for (int nf = 0; nf < 8; nf++) {
            int gr0 = rowBase + warpRow + mf * 16 + (lane >> 2);
            int gc  = colBase + warpCol + nf * 8 + (lane & 3) * 2;
#pragma unroll
            for (int half = 0; half < 2; half++) {
                int gr = gr0 + half * 8;
                if (gr >= M) continue;
                float v0 = acc[mf][nf][half * 2 + 0];
                float v1 = acc[mf][nf][half * 2 + 1];
                if (gc < Nlog)
                    C[(size_t)gr * Nlog + gc] = 1.f / (1.f + __expf(-(v0 + bias[gc])));
                if (gc + 1 < Nlog)
                    C[(size_t)gr * Nlog + gc + 1] = 1.f / (1.f + __expf(-(v1 + bias[gc + 1])));
            }
        }
    }
}

// ---------------- launch ----------------
extern "C" void kernel_launch(void* const* d_in, const int* in_sizes, int n_in,
                              void* d_out, int out_size) {
    const float* x   = (const float*)d_in[0];
    const void*  ei  = d_in[1];
    const float* W1  = (const float*)d_in[2];
    const float* as1 = (const float*)d_in[3];
    const float* ad1 = (const float*)d_in[4];
    const float* b1  = (const float*)d_in[5];
    const float* W2  = (const float*)d_in[6];
    const float* as2 = (const float*)d_in[7];
    const float* ad2 = (const float*)d_in[8];
    const float* b2  = (const float*)d_in[9];
    const float* Wm1 = (const float*)d_in[10];
    const float* bm1 = (const float*)d_in[11];
    const float* Wm2 = (const float*)d_in[12];
    const float* bm2 = (const float*)d_in[13];
    float* out = (float*)d_out;

    void* cntp; cudaGetSymbolAddress(&cntp, g_cnt);
    bf16 *ax, *aext, *b1e, *b2e, *bWc;
    __half* h1;
    float *gas, *gad, *bc;
    cudaGetSymbolAddress((void**)&ax, g_ax);
    cudaGetSymbolAddress((void**)&aext, g_aext);
    cudaGetSymbolAddress((void**)&h1, g_h1);
    cudaGetSymbolAddress((void**)&gas, g_as);
    cudaGetSymbolAddress((void**)&gad, g_ad);
    cudaGetSymbolAddress((void**)&b1e, g_b1e);
    cudaGetSymbolAddress((void**)&b2e, g_b2e);
    cudaGetSymbolAddress((void**)&bWc, g_bWc);
    cudaGetSymbolAddress((void**)&bc, g_bc);

    // one-time infra (same launched work every call)
    static cudaStream_t s2 = nullptr;
    static cudaEvent_t ev1 = nullptr, ev2 = nullptr;
    if (!s2) {
        cudaStreamCreateWithFlags(&s2, cudaStreamNonBlocking);
        cudaEventCreateWithFlags(&ev1, cudaEventDisableTiming);
        cudaEventCreateWithFlags(&ev2, cudaEventDisableTiming);
    }

    const int MB = (Nn + 127) / 128;  // 391
    const int G256_SMEM = 3 * (128 * 40 + 32 * 264) * (int)sizeof(bf16);  // 81408
    cudaFuncSetAttribute(k_g256, cudaFuncAttributeMaxDynamicSharedMemorySize, G256_SMEM);

    // ---- fork point for CSR side-stream ----
    cudaEventRecord(ev1, 0);

    // ---- main stream: convs + layer-1 GEMM + fused-MLP precompute ----
    k_convA<<<(Nn * 128 + 255) / 256, 256>>>(x, ax, Nn, 128);                    // 0
    k_convB<<<(128 * 256 + 255) / 256, 256>>>(W1, b1e, 128, 256, 256);           // 1
    k_convB<<<(256 * 256 + 255) / 256, 256>>>(W2, b2e, 256, 256, 256);           // 2
    k_g256<<<dim3(1, MB), 512, G256_SMEM>>>(ax, b1e, h1, Nn, 384,
                                            as1, ad1, gas, gad);                 // 3
    k_fuse<<<(256 * 128 + 255) / 256, 256>>>(Wm1, bm1, Wm2, bm2, bWc, bc);

    // ---- side stream: CSR build (independent until agg) ----
    cudaStreamWaitEvent(s2, ev1, 0);
    k_detect<<<1, 256, 0, s2>>>((const long long*)ei);
    cudaMemsetAsync(cntp, 0, Nn * sizeof(int), s2);
    k_hist<<<(ETOT + 255) / 256, 256, 0, s2>>>(ei);
    k_scan_block<<<49, 1024, 0, s2>>>();
    k_scan_bsum<<<1, 64, 0, s2>>>(49);
    k_scan_add<<<49, 1024, 0, s2>>>();
    cudaMemsetAsync(cntp, 0, Nn * sizeof(int), s2);
    k_scatter<<<(ETOT + 255) / 256, 256, 0, s2>>>(ei);
    cudaEventRecord(ev2, s2);

    // ---- join: agg needs CSR + layer-1 GEMM ----
    cudaStreamWaitEvent(0, ev2, 0);
    k_agg3<<<Nn, 128>>>(h1, b1, aext);
    // ---- layer 2 ----
    k_g256<<<dim3(1, MB), 512, G256_SMEM>>>(aext, b2e, h1, Nn, 768,
                                            as2, ad2, gas, gad);
    k_agg3<<<Nn, 128>>>(h1, b2, aext);
    // ---- fused MLP head (single GEMM + sigmoid) ----
    k_gmma<128, 4, 2><<<dim3(1, MB), 256>>>(aext, bWc, bc, out, Nn, 768, 128, 121);
}

// round 14
// speedup vs baseline: 1.5754x; 1.1194x over previous
#include <cuda_runtime.h>
#include <cuda_bf16.h>
#include <cuda_fp16.h>
#include <cstdint>
#include <math.h>

#define Nn   50000
#define Ee   800000
#define ETOT 850000
#define HC   256
#define CH   128

typedef __nv_bfloat16 bf16;

// ---------------- static device scratch ----------------
__device__ __align__(16) bf16   g_ax[(size_t)Nn * 256];    // x ext [Ah|Al]
__device__ __align__(16) bf16   g_aext[(size_t)Nn * 512];  // h ext [Ah|Al]
__device__ __align__(16) __half g_h1[(size_t)Nn * HC];     // fp16 h (gather-only)
__device__ __align__(16) bf16   g_b1e[256 * 256];          // [Bh;Bh]
__device__ __align__(16) bf16   g_b2e[512 * 256];
__device__ __align__(16) bf16   g_bWc[512 * 128];          // fused MLP weight ext
__device__ float g_bc[128];
__device__ float g_as[Nn * 4];
__device__ float g_ad[Nn * 4];
__device__ int   g_cnt[Nn];
__device__ int   g_incl[Nn];
__device__ int   g_bsum[64];
__device__ int   g_rowptr[Nn + 1];
__device__ int   g_csrc[ETOT];
__device__ int   g_is64;

// ---------------- edge-index dtype detection ----------------
__global__ void k_detect(const long long* ei) {
    __shared__ int bad;
    if (threadIdx.x == 0) bad = 0;
    __syncthreads();
    long long v = ei[threadIdx.x];
    if (v < 0 || v >= Nn) atomicExch(&bad, 1);
    __syncthreads();
    if (threadIdx.x == 0) g_is64 = bad ? 0 : 1;
}

__device__ __forceinline__ int edge_at(const void* ei, int which, int i) {
    if (g_is64) return (int)((const long long*)ei)[(size_t)which * Ee + i];
    return ((const int*)ei)[(size_t)which * Ee + i];
}

// ---------------- CSR build ----------------
__global__ void k_hist(const void* ei) {
    int i = blockIdx.x * blockDim.x + threadIdx.x;
    if (i >= ETOT) return;
    int d = (i < Ee) ? edge_at(ei, 1, i) : (i - Ee);
    atomicAdd(&g_cnt[d], 1);
}

__global__ void k_scan_block() {
    __shared__ int sh[1024];
    int i = blockIdx.x * 1024 + threadIdx.x;
    int v = (i < Nn) ? g_cnt[i] : 0;
    sh[threadIdx.x] = v;
    __syncthreads();
    for (int off = 1; off < 1024; off <<= 1) {
        int t = (threadIdx.x >= off) ? sh[threadIdx.x - off] : 0;
        __syncthreads();
        sh[threadIdx.x] += t;
        __syncthreads();
    }
    if (i < Nn) g_incl[i] = sh[threadIdx.x];
    if (threadIdx.x == 1023) g_bsum[blockIdx.x] = sh[1023];
}

__global__ void k_scan_bsum(int nb) {
    __shared__ int sh[64];
    int v = (threadIdx.x < nb) ? g_bsum[threadIdx.x] : 0;
    sh[threadIdx.x] = v;
    __syncthreads();
    for (int off = 1; off < 64; off <<= 1) {
        int t = (threadIdx.x >= off) ? sh[threadIdx.x - off] : 0;
        __syncthreads();
        sh[threadIdx.x] += t;
        __syncthreads();
    }
    if (threadIdx.x < nb) g_bsum[threadIdx.x] = sh[threadIdx.x];
}

__global__ void k_scan_add() {
    int i = blockIdx.x * 1024 + threadIdx.x;
    if (i < Nn) {
        int add = blockIdx.x ? g_bsum[blockIdx.x - 1] : 0;
        g_rowptr[i + 1] = g_incl[i] + add;
        if (i == 0) g_rowptr[0] = 0;
    }
}

__global__ void k_scatter(const void* ei) {
    int i = blockIdx.x * blockDim.x + threadIdx.x;
    if (i >= ETOT) return;
    int s, d;
    if (i < Ee) { s = edge_at(ei, 0, i); d = edge_at(ei, 1, i); }
    else        { s = d = i - Ee; }
    int pos = g_rowptr[d] + atomicAdd(&g_cnt[d], 1);
    g_csrc[pos] = s;
}

// ---------------- split-bf16 conversions (2-term: A split, B hi-only) ----------------
__device__ __forceinline__ void split_bf(float v, bf16& hi, bf16& lo) {
    hi = __float2bfloat16(v);
    lo = __float2bfloat16(v - __bfloat162float(hi));
}

// A ext: cols [0,K)=hi, [K,2K)=lo
__global__ void k_convA(const float* __restrict__ X, bf16* __restrict__ out, int M, int K) {
    int idx = blockIdx.x * blockDim.x + threadIdx.x;
    if (idx >= M * K) return;
    int m = idx / K, k = idx % K;
    bf16 hi, lo;
    split_bf(X[idx], hi, lo);
    size_t base = (size_t)m * (2 * K);
    out[base + k] = hi;
    out[base + K + k] = lo;
}

// B ext: rows [0,K)=hi, [K,2K)=hi (duplicated)
__global__ void k_convB(const float* __restrict__ W, bf16* __restrict__ out,
                        int K, int Nsrc, int Nphys) {
    int idx = blockIdx.x * blockDim.x + threadIdx.x;
    if (idx >= K * Nphys) return;
    int k = idx / Nphys, n = idx % Nphys;
    float v = (n < Nsrc) ? W[k * Nsrc + n] : 0.f;
    bf16 hi = __float2bfloat16(v);
    out[(size_t)k * Nphys + n] = hi;
    out[(size_t)(K + k) * Nphys + n] = hi;
}

// ---------------- fused MLP weight precompute: Wc = Wm1@Wm2, bc = bm1@Wm2 + bm2 ----------------
// Output ext: rows [0,256)=hi, [256,512)=hi.
__global__ void k_fuse(const float* __restrict__ Wm1, const float* __restrict__ bm1,
                       const float* __restrict__ Wm2, const float* __restrict__ bm2,
                       bf16* __restrict__ oute, float* __restrict__ bc) {
    int idx = blockIdx.x * blockDim.x + threadIdx.x;
    if (idx >= 256 * 128) return;
    int k = idx >> 7, n = idx & 127;
    float v = 0.f;
    if (n < 121) {
#pragma unroll 8
        for (int j = 0; j < 64; j++) v += Wm1[k * 64 + j] * Wm2[j * 121 + n];
    }
    bf16 hi = __float2bfloat16(v);
    oute[(size_t)k * 128 + n] = hi;
    oute[(size_t)(256 + k) * 128 + n] = hi;
    if (k == 0) {
        float b = 0.f;
        if (n < 121) {
#pragma unroll 8
            for (int j = 0; j < 64; j++) b += bm1[j] * Wm2[j * 121 + n];
            b += bm2[n];
        }
        bc[n] = b;
    }
}

// ---------------- single-pass online-softmax aggregation (fp16 gather, 2-term ext out) ----------------
__global__ __launch_bounds__(128)
void k_agg3(const __half* __restrict__ h,
            const float* __restrict__ bias,
            bf16* __restrict__ outext) {
    int n = blockIdx.x;
    int tid = threadIdx.x;
    int w = tid >> 5, l = tid & 31;
    int beg = g_rowptr[n], end = g_rowptr[n + 1];
    float adv = g_ad[n * 4 + w];

    __shared__ int   s_src[CH];
    __shared__ float s_t[CH][4];

    float acc0 = 0.f, acc1 = 0.f, den = 0.f, m = -1e30f;

    for (int c0 = beg; c0 < end; c0 += CH) {
        int cnt = min(CH, end - c0);
        __syncthreads();
        for (int i = tid; i < cnt; i += 128) s_src[i] = g_csrc[c0 + i];
        __syncthreads();

        float cm = -1e30f;
        for (int i = l; i < cnt; i += 32) {
            float t = g_as[s_src[i] * 4 + w] + adv;
            t = (t > 0.f) ? t : 0.2f * t;
            s_t[i][w] = t;
            cm = fmaxf(cm, t);
        }
        for (int o = 16; o; o >>= 1) cm = fmaxf(cm, __shfl_xor_sync(0xffffffffu, cm, o));
        __syncwarp();

        float nm = fmaxf(m, cm);
        float sc = __expf(m - nm);
        acc0 *= sc; acc1 *= sc; den *= sc;
        m = nm;

#pragma unroll 4
        for (int e = 0; e < cnt; e++) {
            float wt = __expf(s_t[e][w] - m);
            den += wt;
            __half2 hv = *(const __half2*)(h + (size_t)s_src[e] * HC + w * 64 + 2 * l);
            float2 v = __half22float2(hv);
            acc0 += wt * v.x;
            acc1 += wt * v.y;
        }
    }

    float inv = 1.f / (den + 1e-16f);
    int c0 = w * 64 + 2 * l, c1 = c0 + 1;
    float v0 = fmaxf(acc0 * inv + bias[c0], 0.f);
    float v1 = fmaxf(acc1 * inv + bias[c1], 0.f);
    bf16 h0, l0, h1b, l1;
    split_bf(v0, h0, l0);
    split_bf(v1, h1b, l1);
    size_t base = (size_t)n * 512;
    outext[base + c0] = h0;  outext[base + 256 + c0] = l0;
    outext[base + c1] = h1b; outext[base + 256 + c1] = l1;
}

// ---------------- mma helpers (bf16) ----------------
__device__ __forceinline__ unsigned smem_u32(const void* p) {
    return (unsigned)__cvta_generic_to_shared(p);
}
__device__ __forceinline__ void ldsm4(unsigned addr, unsigned& r0, unsigned& r1,
                                      unsigned& r2, unsigned& r3) {
    asm volatile("ldmatrix.sync.aligned.m8n8.x4.shared.b16 {%0,%1,%2,%3},[%4];"
                 : "=r"(r0), "=r"(r1), "=r"(r2), "=r"(r3) : "r"(addr));
}
__device__ __forceinline__ void ldsm4t(unsigned addr, unsigned& r0, unsigned& r1,
                                       unsigned& r2, unsigned& r3) {
    asm volatile("ldmatrix.sync.aligned.m8n8.x4.trans.shared.b16 {%0,%1,%2,%3},[%4];"
                 : "=r"(r0), "=r"(r1), "=r"(r2), "=r"(r3) : "r"(addr));
}
__device__ __forceinline__ void mma16816(float& c0, float& c1, float& c2, float& c3,
                                         unsigned a0, unsigned a1, unsigned a2, unsigned a3,
                                         unsigned b0, unsigned b1) {
    asm volatile("mma.sync.aligned.m16n8k16.row.col.f32.bf16.bf16.f32 "
                 "{%0,%1,%2,%3},{%4,%5,%6,%7},{%8,%9},{%0,%1,%2,%3};"
                 : "+f"(c0), "+f"(c1), "+f"(c2), "+f"(c3)
                 : "r"(a0), "r"(a1), "r"(a2), "r"(a3), "r"(b0), "r"(b1));
}
__device__ __forceinline__ void cp16(unsigned dst, const void* src) {
    asm volatile("cp.async.cg.shared.global [%0], [%1], 16;" :: "r"(dst), "l"(src));
}
__device__ __forceinline__ void cp_commit() {
    asm volatile("cp.async.commit_group;" ::: "memory");
}
__device__ __forceinline__ void cp_wait1() {
    asm volatile("cp.async.wait_group 1;" ::: "memory");
}

// ---------------- 128x256 3-stage cp.async bf16 GEMM + fused attention dots ----------------
// 512 threads, 16 warps: 4 along M x 4 along N, 32x64 per warp. fp16 C out.
__global__ __launch_bounds__(512)
void k_g256(const bf16* __restrict__ A, const bf16* __restrict__ B,
            __half* __restrict__ C, int M, int Kext,
            const float* __restrict__ asrc, const float* __restrict__ adst,
            float* __restrict__ gas, float* __restrict__ gad) {
    constexpr int LDA = 40;
    constexpr int LDB = 264;
    constexpr int ASZ = 128 * LDA;
    constexpr int BSZ = 32 * LDB;

    extern __shared__ bf16 sm[];
    bf16* As = sm;
    bf16* Bs = sm + 3 * ASZ;

    const int tid = threadIdx.x;
    const int warp = tid >> 5, lane = tid & 31;
    const int wm = warp & 3, wn = warp >> 2;
    const int warpRow = wm * 32;
    const int warpCol = wn * 64;
    const int rowBase = blockIdx.y * 128;

    float acc[2][8][4];
#pragma unroll
    for (int i = 0; i < 2; i++)
#pragma unroll
        for (int j = 0; j < 8; j++)
#pragma unroll
            for (int q = 0; q < 4; q++) acc[i][j][q] = 0.f;

    const int nsteps = Kext / 32;
    const int arow = tid >> 2, aq = tid & 3;

    auto load_stage = [&](int st, int k0) {
        unsigned abase = smem_u32(&As[st * ASZ]);
        unsigned bbase = smem_u32(&Bs[st * BSZ]);
        {
            int gr = min(rowBase + arow, M - 1);
            cp16(abase + (arow * LDA + aq * 8) * 2,
                 A + (size_t)gr * Kext + k0 + aq * 8);
        }
#pragma unroll
        for (int i = 0; i < 2; i++) {
            int idx = tid + i * 512;
            int k = idx >> 5, qb = idx & 31;
            cp16(bbase + (k * LDB + qb * 8) * 2,
                 B + (size_t)(k0 + k) * 256 + qb * 8);
        }
    };

    load_stage(0, 0);
    cp_commit();
    if (1 < nsteps) load_stage(1, 32);
    cp_commit();
    cp_wait1();
    __syncthreads();

    for (int s = 0; s < nsteps; ++s) {
        int buf = s % 3;
        unsigned aB = smem_u32(&As[buf * ASZ]);
        unsigned bB = smem_u32(&Bs[buf * BSZ]);

#pragma unroll
        for (int ks = 0; ks < 32; ks += 16) {
            unsigned a[2][4];
#pragma unroll
            for (int mf = 0; mf < 2; mf++) {
                int row = warpRow + mf * 16 + (lane & 15);
                int col = ks + ((lane & 16) ? 8 : 0);
                ldsm4(aB + (row * LDA + col) * 2, a[mf][0], a[mf][1], a[mf][2], a[mf][3]);
            }
            unsigned bb[8][2];
#pragma unroll
            for (int g = 0; g < 4; g++) {
                int kk = ks + (lane & 15);
                int nn = warpCol + g * 16 + ((lane & 16) ? 8 : 0);
                unsigned r0, r1, r2, r3;
                ldsm4t(bB + (kk * LDB + nn) * 2, r0, r1, r2, r3);
                bb[2 * g][0] = r0; bb[2 * g][1] = r1;
                bb[2 * g + 1][0] = r2; bb[2 * g + 1][1] = r3;
            }
#pragma unroll
            for (int mf = 0; mf < 2; mf++)
#pragma unroll
                for (int nf = 0; nf < 8; nf++)
                    mma16816(acc[mf][nf][0], acc[mf][nf][1], acc[mf][nf][2], acc[mf][nf][3],
                             a[mf][0], a[mf][1], a[mf][2], a[mf][3],
                             bb[nf][0], bb[nf][1]);
        }

        int nx = s + 2;
        if (nx < nsteps) load_stage(nx % 3, nx * 32);
        cp_commit();
        cp_wait1();
        __syncthreads();
    }

    // ---- epilogue: fp16 C stores ----
#pragma unroll
    for (int mf = 0; mf < 2; mf++) {
#pragma unroll
        for (int nf = 0; nf < 8; nf++) {
            int gr0 = rowBase + warpRow + mf * 16 + (lane >> 2);
            int gc  = warpCol + nf * 8 + (lane & 3) * 2;
#pragma unroll
            for (int half = 0; half < 2; half++) {
                int gr = gr0 + half * 8;
                if (gr >= M) continue;
                __half2 hv = __floats2half2_rn(acc[mf][nf][half * 2],
                                               acc[mf][nf][half * 2 + 1]);
                *(__half2*)(C + (size_t)gr * 256 + gc) = hv;
            }
        }
    }

    // ---- fused attention dot products ----
    float av[16], dv[16];
#pragma unroll
    for (int nf = 0; nf < 8; nf++) {
        int gc = warpCol + nf * 8 + (lane & 3) * 2;
        av[nf * 2 + 0] = asrc[gc];     av[nf * 2 + 1] = asrc[gc + 1];
        dv[nf * 2 + 0] = adst[gc];     dv[nf * 2 + 1] = adst[gc + 1];
    }
#pragma unroll
    for (int mf = 0; mf < 2; mf++) {
#pragma unroll
        for (int half = 0; half < 2; half++) {
            int gr = rowBase + warpRow + mf * 16 + (lane >> 2) + half * 8;
            float s = 0.f, d = 0.f;
#pragma unroll
            for (int nf = 0; nf < 8; nf++) {
                float v0 = acc[mf][nf][half * 2], v1 = acc[mf][nf][half * 2 + 1];
                s += v0 * av[nf * 2] + v1 * av[nf * 2 + 1];
                d += v0 * dv[nf * 2] + v1 * dv[nf * 2 + 1];
            }
            s += __shfl_xor_sync(0xffffffffu, s, 1);
            s += __shfl_xor_sync(0xffffffffu, s, 2);
            d += __shfl_xor_sync(0xffffffffu, d, 1);
            d += __shfl_xor_sync(0xffffffffu, d, 2);
            if ((lane & 3) == 0 && gr < M) {
                gas[gr * 4 + wn] = s;
                gad[gr * 4 + wn] = d;
            }
        }
    }
}

// ---------------- mma.sync bf16 GEMM (final fused MLP, sigmoid out) ----------------
template <int BN, int WM, int MF>
__global__ __launch_bounds__(256)
void k_gmma(const bf16* __restrict__ A, const bf16* __restrict__ B,
            const float* __restrict__ bias, float* __restrict__ C,
            int M, int Kext, int NB, int Nlog) {
    constexpr int LDA = 40;
    constexpr int LDB = BN + 8;
    constexpr int NB4 = BN * 32 / 2048;

    __shared__ bf16 As[2][128 * LDA];
    __shared__ bf16 Bs[2][32 * LDB];

    const int tid = threadIdx.x;
    const int warp = tid >> 5, lane = tid & 31;
    const int wm = warp % WM, wn = warp / WM;
    const int warpRow = wm * (MF * 16);
    const int warpCol = wn * 64;
    const int rowBase = blockIdx.y * 128;
    const int colBase = blockIdx.x * BN;

    float acc[MF][8][4];
#pragma unroll
    for (int i = 0; i < MF; i++)
#pragma unroll
        for (int j = 0; j < 8; j++)
#pragma unroll
            for (int q = 0; q < 4; q++) acc[i][j][q] = 0.f;

    const int nsteps = Kext / 32;
    int4 pa[2], pb[NB4];

#pragma unroll
    for (int i = 0; i < 2; i++) {
        int idx = tid + i * 256;
        int row = idx >> 2, q = idx & 3;
        int gr = rowBase + row;
        int4 v = (gr < M) ? *(const int4*)(A + (size_t)gr * Kext + q * 8)
                          : make_int4(0, 0, 0, 0);
        *(int4*)(&As[0][row * LDA + q * 8]) = v;
    }
#pragma unroll
    for (int i = 0; i < NB4; i++) {
        int idx = tid + i * 256;
        int k = idx / (BN / 8), q = idx % (BN / 8);
        int4 v = *(const int4*)(B + (size_t)k * NB + colBase + q * 8);
        *(int4*)(&Bs[0][k * LDB + q * 8]) = v;
    }
    __syncthreads();

    for (int s = 0; s < nsteps; ++s) {
        int buf = s & 1;
        bool more = (s + 1 < nsteps);
        int k0n = (s + 1) * 32;

        if (more) {
#pragma unroll
            for (int i = 0; i < 2; i++) {
                int idx = tid + i * 256;
                int row = idx >> 2, q = idx & 3;
                int gr = rowBase + row;
                pa[i] = (gr < M) ? *(const int4*)(A + (size_t)gr * Kext + k0n + q * 8)
                                 : make_int4(0, 0, 0, 0);
            }
#pragma unroll
            for (int i = 0; i < NB4; i++) {
                int idx = tid + i * 256;
                int k = idx / (BN / 8), q = idx % (BN / 8);
                pb[i] = *(const int4*)(B + (size_t)(k0n + k) * NB + colBase + q * 8);
            }
        }

        unsigned aB = smem_u32(&As[buf][0]);
        unsigned bB = smem_u32(&Bs[buf][0]);

#pragma unroll
        for (int ks = 0; ks < 32; ks += 16) {
            unsigned a[MF][4];
#pragma unroll
            for (int mf = 0; mf < MF; mf++) {
                int row = warpRow + mf * 16 + (lane & 15);
                int col = ks + ((lane & 16) ? 8 : 0);
                ldsm4(aB + (row * LDA + col) * 2, a[mf][0], a[mf][1], a[mf][2], a[mf][3]);
            }
            unsigned bb[8][2];
#pragma unroll
            for (int g = 0; g < 4; g++) {
                int kk = ks + (lane & 15);
                int nn = warpCol + g * 16 + ((lane & 16) ? 8 : 0);
                unsigned r0, r1, r2, r3;
                ldsm4t(bB + (kk * LDB + nn) * 2, r0, r1, r2, r3);
                bb[2 * g][0] = r0; bb[2 * g][1] = r1;
                bb[2 * g + 1][0] = r2; bb[2 * g + 1][1] = r3;
            }
#pragma unroll
            for (int mf = 0; mf < MF; mf++)
#pragma unroll
                for (int nf = 0; nf < 8; nf++)
                    mma16816(acc[mf][nf][0], acc[mf][nf][1], acc[mf][nf][2], acc[mf][nf][3],
                             a[mf][0], a[mf][1], a[mf][2], a[mf][3],
                             bb[nf][0], bb[nf][1]);
        }

        if (more) {
            int nb = buf ^ 1;
#pragma unroll
            for (int i = 0; i < 2; i++) {
                int idx = tid + i * 256;
                int row = idx >> 2, q = idx & 3;
                *(int4*)(&As[nb][row * LDA + q * 8]) = pa[i];
            }
#pragma unroll
            for (int i = 0; i < NB4; i++) {
                int idx = tid + i * 256;
                int k = idx / (BN / 8), q = idx % (BN / 8);
                *(int4*)(&Bs[nb][k * LDB + q * 8]) = pb[i];
            }
        }
        __syncthreads();
    }

#pragma unroll
    for (int mf = 0; mf < MF; mf++) {
#pragma unroll
        for (int nf = 0; nf < 8; nf++) {
            int gr0 = rowBase + warpRow + mf * 16 + (lane >> 2);
            int gc  = colBase + warpCol + nf * 8 + (lane & 3) * 2;
#pragma unroll
            for (int half = 0; half < 2; half++) {
                int gr = gr0 + half * 8;
                if (gr >= M) continue;
                float v0 = acc[mf][nf][half * 2 + 0];
                float v1 = acc[mf][nf][half * 2 + 1];
                if (gc < Nlog)
                    C[(size_t)gr * Nlog + gc] = 1.f / (1.f + __expf(-(v0 + bias[gc])));
                if (gc + 1 < Nlog)
                    C[(size_t)gr * Nlog + gc + 1] = 1.f / (1.f + __expf(-(v1 + bias[gc + 1])));
            }
        }
    }
}

// ---------------- launch ----------------
extern "C" void kernel_launch(void* const* d_in, const int* in_sizes, int n_in,
                              void* d_out, int out_size) {
    const float* x   = (const float*)d_in[0];
    const void*  ei  = d_in[1];
    const float* W1  = (const float*)d_in[2];
    const float* as1 = (const float*)d_in[3];
    const float* ad1 = (const float*)d_in[4];
    const float* b1  = (const float*)d_in[5];
    const float* W2  = (const float*)d_in[6];
    const float* as2 = (const float*)d_in[7];
    const float* ad2 = (const float*)d_in[8];
    const float* b2  = (const float*)d_in[9];
    const float* Wm1 = (const float*)d_in[10];
    const float* bm1 = (const float*)d_in[11];
    const float* Wm2 = (const float*)d_in[12];
    const float* bm2 = (const float*)d_in[13];
    float* out = (float*)d_out;

    void* cntp; cudaGetSymbolAddress(&cntp, g_cnt);
    bf16 *ax, *aext, *b1e, *b2e, *bWc;
    __half* h1;
    float *gas, *gad, *bc;
    cudaGetSymbolAddress((void**)&ax, g_ax);
    cudaGetSymbolAddress((void**)&aext, g_aext);
    cudaGetSymbolAddress((void**)&h1, g_h1);
    cudaGetSymbolAddress((void**)&gas, g_as);
    cudaGetSymbolAddress((void**)&gad, g_ad);
    cudaGetSymbolAddress((void**)&b1e, g_b1e);
    cudaGetSymbolAddress((void**)&b2e, g_b2e);
    cudaGetSymbolAddress((void**)&bWc, g_bWc);
    cudaGetSymbolAddress((void**)&bc, g_bc);

    static cudaStream_t s2 = nullptr;
    static cudaEvent_t ev1 = nullptr, ev2 = nullptr;
    if (!s2) {
        cudaStreamCreateWithFlags(&s2, cudaStreamNonBlocking);
        cudaEventCreateWithFlags(&ev1, cudaEventDisableTiming);
        cudaEventCreateWithFlags(&ev2, cudaEventDisableTiming);
    }

    const int MB = (Nn + 127) / 128;  // 391
    const int G256_SMEM = 3 * (128 * 40 + 32 * 264) * (int)sizeof(bf16);  // 81408
    cudaFuncSetAttribute(k_g256, cudaFuncAttributeMaxDynamicSharedMemorySize, G256_SMEM);

    // ---- fork point for CSR side-stream ----
    cudaEventRecord(ev1, 0);

    // ---- main stream ----
    k_convA<<<(Nn * 128 + 255) / 256, 256>>>(x, ax, Nn, 128);
    k_convB<<<(128 * 256 + 255) / 256, 256>>>(W1, b1e, 128, 256, 256);
    k_convB<<<(256 * 256 + 255) / 256, 256>>>(W2, b2e, 256, 256, 256);
    k_g256<<<dim3(1, MB), 512, G256_SMEM>>>(ax, b1e, h1, Nn, 256,
                                            as1, ad1, gas, gad);
    k_fuse<<<(256 * 128 + 255) / 256, 256>>>(Wm1, bm1, Wm2, bm2, bWc, bc);

    // ---- side stream: CSR build ----
    cudaStreamWaitEvent(s2, ev1, 0);
    k_detect<<<1, 256, 0, s2>>>((const long long*)ei);
    cudaMemsetAsync(cntp, 0, Nn * sizeof(int), s2);
    k_hist<<<(ETOT + 255) / 256, 256, 0, s2>>>(ei);
    k_scan_block<<<49, 1024, 0, s2>>>();
    k_scan_bsum<<<1, 64, 0, s2>>>(49);
    k_scan_add<<<49, 1024, 0, s2>>>();
    cudaMemsetAsync(cntp, 0, Nn * sizeof(int), s2);
    k_scatter<<<(ETOT + 255) / 256, 256, 0, s2>>>(ei);
    cudaEventRecord(ev2, s2);

    // ---- join ----
    cudaStreamWaitEvent(0, ev2, 0);
    k_agg3<<<Nn, 128>>>(h1, b1, aext);
    // ---- layer 2 ----
    k_g256<<<dim3(1, MB), 512, G256_SMEM>>>(aext, b2e, h1, Nn, 512,
                                            as2, ad2, gas, gad);
    k_agg3<<<Nn, 128>>>(h1, b2, aext);
    // ---- fused MLP head ----
    k_gmma<128, 4, 2><<<dim3(1, MB), 256>>>(aext, bWc, bc, out, Nn, 512, 128, 121);
}

// round 16
// speedup vs baseline: 1.6086x; 1.0211x over previous
#include <cuda_runtime.h>
#include <cuda_bf16.h>
#include <cuda_fp16.h>
#include <cstdint>
#include <math.h>

#define Nn   50000
#define Ee   800000
#define ETOT 850000
#define HC   256
#define CH   128

typedef __nv_bfloat16 bf16;

// ---------------- static device scratch ----------------
__device__ __align__(16) bf16   g_ax[(size_t)Nn * 256];    // x ext [Ah|Al]
__device__ __align__(16) bf16   g_aext[(size_t)Nn * 512];  // h ext [Ah|Al]
__device__ __align__(16) __half g_h1[(size_t)Nn * HC];     // fp16 h (gather-only)
__device__ __align__(16) bf16   g_b1e[256 * 256];          // [Bh;Bh]
__device__ __align__(16) bf16   g_b2e[512 * 256];
__device__ __align__(16) bf16   g_bWc[512 * 128];          // fused MLP weight ext
__device__ float g_bc[128];
__device__ float g_as[Nn * 4];
__device__ float g_ad[Nn * 4];
__device__ float g_gmax[4];
__device__ int   g_cnt[Nn];
__device__ int   g_incl[Nn];
__device__ int   g_bsum[64];
__device__ int   g_rowptr[Nn + 1];
__device__ int   g_csrc[ETOT];
__device__ int   g_is64;

__device__ __forceinline__ void atomicMaxF(float* a, float v) {
    int* ai = (int*)a;
    int old = *ai;
    while (__int_as_float(old) < v) {
        int assumed = old;
        old = atomicCAS(ai, assumed, __float_as_int(v));
        if (old == assumed) break;
    }
}

// ---------------- edge-index dtype detection ----------------
__global__ void k_detect(const long long* ei) {
    __shared__ int bad;
    if (threadIdx.x == 0) bad = 0;
    __syncthreads();
    long long v = ei[threadIdx.x];
    if (v < 0 || v >= Nn) atomicExch(&bad, 1);
    __syncthreads();
    if (threadIdx.x == 0) g_is64 = bad ? 0 : 1;
}

__device__ __forceinline__ int edge_at(const void* ei, int which, int i) {
    if (g_is64) return (int)((const long long*)ei)[(size_t)which * Ee + i];
    return ((const int*)ei)[(size_t)which * Ee + i];
}

// ---------------- CSR build ----------------
__global__ void k_hist(const void* ei) {
    int i = blockIdx.x * blockDim.x + threadIdx.x;
    if (i >= ETOT) return;
    int d = (i < Ee) ? edge_at(ei, 1, i) : (i - Ee);
    atomicAdd(&g_cnt[d], 1);
}

__global__ void k_scan_block() {
    __shared__ int sh[1024];
    int i = blockIdx.x * 1024 + threadIdx.x;
    int v = (i < Nn) ? g_cnt[i] : 0;
    sh[threadIdx.x] = v;
    __syncthreads();
    for (int off = 1; off < 1024; off <<= 1) {
        int t = (threadIdx.x >= off) ? sh[threadIdx.x - off] : 0;
        __syncthreads();
        sh[threadIdx.x] += t;
        __syncthreads();
    }
    if (i < Nn) g_incl[i] = sh[threadIdx.x];
    if (threadIdx.x == 1023) g_bsum[blockIdx.x] = sh[1023];
}

__global__ void k_scan_bsum(int nb) {
    __shared__ int sh[64];
    int v = (threadIdx.x < nb) ? g_bsum[threadIdx.x] : 0;
    sh[threadIdx.x] = v;
    __syncthreads();
    for (int off = 1; off < 64; off <<= 1) {
        int t = (threadIdx.x >= off) ? sh[threadIdx.x - off] : 0;
        __syncthreads();
        sh[threadIdx.x] += t;
        __syncthreads();
    }
    if (threadIdx.x < nb) g_bsum[threadIdx.x] = sh[threadIdx.x];
}

__global__ void k_scan_add() {
    int i = blockIdx.x * 1024 + threadIdx.x;
    if (i < Nn) {
        int add = blockIdx.x ? g_bsum[blockIdx.x - 1] : 0;
        g_rowptr[i + 1] = g_incl[i] + add;
        if (i == 0) g_rowptr[0] = 0;
    }
}

__global__ void k_scatter(const void* ei) {
    int i = blockIdx.x * blockDim.x + threadIdx.x;
    if (i >= ETOT) return;
    int s, d;
    if (i < Ee) { s = edge_at(ei, 0, i); d = edge_at(ei, 1, i); }
    else        { s = d = i - Ee; }
    int pos = g_rowptr[d] + atomicAdd(&g_cnt[d], 1);
    g_csrc[pos] = s;
}

// ---------------- conversions ----------------
__device__ __forceinline__ void split_bf(float v, bf16& hi, bf16& lo) {
    hi = __float2bfloat16(v);
    lo = __float2bfloat16(v - __bfloat162float(hi));
}

__global__ void k_convA(const float* __restrict__ X, bf16* __restrict__ out, int M, int K) {
    int idx = blockIdx.x * blockDim.x + threadIdx.x;
    if (idx >= M * K) return;
    int m = idx / K, k = idx % K;
    bf16 hi, lo;
    split_bf(X[idx], hi, lo);
    size_t base = (size_t)m * (2 * K);
    out[base + k] = hi;
    out[base + K + k] = lo;
}

__global__ void k_convB(const float* __restrict__ W, bf16* __restrict__ out,
                        int K, int Nsrc, int Nphys) {
    int idx = blockIdx.x * blockDim.x + threadIdx.x;
    if (idx >= K * Nphys) return;
    int k = idx / Nphys, n = idx % Nphys;
    float v = (n < Nsrc) ? W[k * Nsrc + n] : 0.f;
    bf16 hi = __float2bfloat16(v);
    out[(size_t)k * Nphys + n] = hi;
    out[(size_t)(K + k) * Nphys + n] = hi;
}

// reset gmax
__global__ void k_rst() {
    if (threadIdx.x < 4) g_gmax[threadIdx.x] = -1e30f;
}

// ---------------- fused MLP weight precompute ----------------
__global__ void k_fuse(const float* __restrict__ Wm1, const float* __restrict__ bm1,
                       const float* __restrict__ Wm2, const float* __restrict__ bm2,
                       bf16* __restrict__ oute, float* __restrict__ bc) {
    int idx = blockIdx.x * blockDim.x + threadIdx.x;
    if (idx >= 256 * 128) return;
    int k = idx >> 7, n = idx & 127;
    float v = 0.f;
    if (n < 121) {
#pragma unroll 8
        for (int j = 0; j < 64; j++) v += Wm1[k * 64 + j] * Wm2[j * 121 + n];
    }
    bf16 hi = __float2bfloat16(v);
    oute[(size_t)k * 128 + n] = hi;
    oute[(size_t)(256 + k) * 128 + n] = hi;
    if (k == 0) {
        float b = 0.f;
        if (n < 121) {
#pragma unroll 8
            for (int j = 0; j < 64; j++) b += bm1[j] * Wm2[j * 121 + n];
            b += bm2[n];
        }
        bc[n] = b;
    }
}

// ---------------- warp-striped aggregation (global-max shift, no max pass) ----------------
// 128 threads; warp w gathers edges e ≡ w (mod 4), lane owns channels 8l..8l+7.
__global__ __launch_bounds__(128)
void k_agg4(const __half* __restrict__ h,
            const float* __restrict__ bias,
            bf16* __restrict__ outext) {
    int n = blockIdx.x;
    int tid = threadIdx.x;
    int w = tid >> 5, lane = tid & 31;
    int hh = tid & 3;            // head this thread stages
    int gh = lane >> 3;          // head of this lane's gather channels
    int beg = g_rowptr[n], end = g_rowptr[n + 1];

    __shared__ int   s_src[CH];
    __shared__ float s_wt[CH][5];
    __shared__ float s_part[4][256];
    __shared__ float s_den[4];

    float adv = g_ad[n * 4 + hh];
    float ms = g_gmax[hh] + adv;                 // upper bound of logits, pre-leaky
    ms = (ms > 0.f) ? ms : 0.2f * ms;            // leaky is monotone

    float acc[8];
#pragma unroll
    for (int j = 0; j < 8; j++) acc[j] = 0.f;
    float den = 0.f;

    for (int c0 = beg; c0 < end; c0 += CH) {
        int cnt = min(CH, end - c0);
        __syncthreads();                         // protect smem reuse
        for (int i = tid; i < cnt; i += 128) s_src[i] = g_csrc[c0 + i];
        __syncthreads();

        // stage exp-weights; thread's head fixed (= tid&3)
        for (int i = tid; i < cnt * 4; i += 128) {
            int e = i >> 2;
            float t = g_as[s_src[e] * 4 + hh] + adv;
            t = (t > 0.f) ? t : 0.2f * t;
            s_wt[e][hh] = __expf(t - ms);
        }
        __syncthreads();

        // den for head w (lane-strided over staged column; stride-5 pad -> conflict-free)
        for (int i = lane; i < cnt; i += 32) den += s_wt[i][w];

        // gather: warp-striped edges, full fp16 row per edge (int4/lane)
#pragma unroll 4
        for (int e = w; e < cnt; e += 4) {
            float wt = s_wt[e][gh];
            const int4* rp = (const int4*)(h + (size_t)s_src[e] * HC);
            int4 hv = rp[lane];
            __half2* hp = (__half2*)&hv;
#pragma unroll
            for (int q = 0; q < 4; q++) {
                float2 v = __half22float2(hp[q]);
                acc[2 * q]     += wt * v.x;
                acc[2 * q + 1] += wt * v.y;
            }
        }
    }

    // reduce den within warp (full den for head w)
    for (int o = 16; o; o >>= 1) den += __shfl_xor_sync(0xffffffffu, den, o);

    // cross-warp channel reduction
#pragma unroll
    for (int j = 0; j < 8; j++) s_part[w][lane * 8 + j] = acc[j];
    if (lane == 0) s_den[w] = den;
    __syncthreads();

    int c0i = 2 * tid, c1i = c0i + 1;
    float inv = 1.f / fmaxf(s_den[tid >> 5], 1e-30f);
    float a0 = s_part[0][c0i] + s_part[1][c0i] + s_part[2][c0i] + s_part[3][c0i];
    float a1 = s_part[0][c1i] + s_part[1][c1i] + s_part[2][c1i] + s_part[3][c1i];
    float v0 = fmaxf(a0 * inv + bias[c0i], 0.f);
    float v1 = fmaxf(a1 * inv + bias[c1i], 0.f);
    bf16 h0, l0, h1b, l1;
    split_bf(v0, h0, l0);
    split_bf(v1, h1b, l1);
    size_t base = (size_t)n * 512;
    outext[base + c0i] = h0;  outext[base + 256 + c0i] = l0;
    outext[base + c1i] = h1b; outext[base + 256 + c1i] = l1;
}

// ---------------- mma helpers (bf16) ----------------
__device__ __forceinline__ unsigned smem_u32(const void* p) {
    return (unsigned)__cvta_generic_to_shared(p);
}
__device__ __forceinline__ void ldsm4(unsigned addr, unsigned& r0, unsigned& r1,
                                      unsigned& r2, unsigned& r3) {
    asm volatile("ldmatrix.sync.aligned.m8n8.x4.shared.b16 {%0,%1,%2,%3},[%4];"
                 : "=r"(r0), "=r"(r1), "=r"(r2), "=r"(r3) : "r"(addr));
}
__device__ __forceinline__ void ldsm4t(unsigned addr, unsigned& r0, unsigned& r1,
                                       unsigned& r2, unsigned& r3) {
    asm volatile("ldmatrix.sync.aligned.m8n8.x4.trans.shared.b16 {%0,%1,%2,%3},[%4];"
                 : "=r"(r0), "=r"(r1), "=r"(r2), "=r"(r3) : "r"(addr));
}
__device__ __forceinline__ void mma16816(float& c0, float& c1, float& c2, float& c3,
                                         unsigned a0, unsigned a1, unsigned a2, unsigned a3,
                                         unsigned b0, unsigned b1) {
    asm volatile("mma.sync.aligned.m16n8k16.row.col.f32.bf16.bf16.f32 "
                 "{%0,%1,%2,%3},{%4,%5,%6,%7},{%8,%9},{%0,%1,%2,%3};"
                 : "+f"(c0), "+f"(c1), "+f"(c2), "+f"(c3)
                 : "r"(a0), "r"(a1), "r"(a2), "r"(a3), "r"(b0), "r"(b1));
}
__device__ __forceinline__ void cp16(unsigned dst, const void* src) {
    asm volatile("cp.async.cg.shared.global [%0], [%1], 16;" :: "r"(dst), "l"(src));
}
__device__ __forceinline__ void cp_commit() {
    asm volatile("cp.async.commit_group;" ::: "memory");
}
__device__ __forceinline__ void cp_wait1() {
    asm volatile("cp.async.wait_group 1;" ::: "memory");
}

// ---------------- 128x256 3-stage cp.async bf16 GEMM + fused attn dots + gmax ----------------
__global__ __launch_bounds__(512)
void k_g256(const bf16* __restrict__ A, const bf16* __restrict__ B,
            __half* __restrict__ C, int M, int Kext,
            const float* __restrict__ asrc, const float* __restrict__ adst,
            float* __restrict__ gas, float* __restrict__ gad,
            float* __restrict__ gmax) {
    constexpr int LDA = 40;
    constexpr int LDB = 264;
    constexpr int ASZ = 128 * LDA;
    constexpr int BSZ = 32 * LDB;

    extern __shared__ bf16 sm[];
    bf16* As = sm;
    bf16* Bs = sm + 3 * ASZ;

    const int tid = threadIdx.x;
    const int warp = tid >> 5, lane = tid & 31;
    const int wm = warp & 3, wn = warp >> 2;
    const int warpRow = wm * 32;
    const int warpCol = wn * 64;
    const int rowBase = blockIdx.y * 128;

    float acc[2][8][4];
#pragma unroll
    for (int i = 0; i < 2; i++)
#pragma unroll
        for (int j = 0; j < 8; j++)
#pragma unroll
            for (int q = 0; q < 4; q++) acc[i][j][q] = 0.f;

    const int nsteps = Kext / 32;
    const int arow = tid >> 2, aq = tid & 3;

    auto load_stage = [&](int st, int k0) {
        unsigned abase = smem_u32(&As[st * ASZ]);
        unsigned bbase = smem_u32(&Bs[st * BSZ]);
        {
            int gr = min(rowBase + arow, M - 1);
            cp16(abase + (arow * LDA + aq * 8) * 2,
                 A + (size_t)gr * Kext + k0 + aq * 8);
        }
#pragma unroll
        for (int i = 0; i < 2; i++) {
            int idx = tid + i * 512;
            int k = idx >> 5, qb = idx & 31;
            cp16(bbase + (k * LDB + qb * 8) * 2,
                 B + (size_t)(k0 + k) * 256 + qb * 8);
        }
    };

    load_stage(0, 0);
    cp_commit();
    if (1 < nsteps) load_stage(1, 32);
    cp_commit();
    cp_wait1();
    __syncthreads();

    for (int s = 0; s < nsteps; ++s) {
        int buf = s % 3;
        unsigned aB = smem_u32(&As[buf * ASZ]);
        unsigned bB = smem_u32(&Bs[buf * BSZ]);

#pragma unroll
        for (int ks = 0; ks < 32; ks += 16) {
            unsigned a[2][4];
#pragma unroll
            for (int mf = 0; mf < 2; mf++) {
                int row = warpRow + mf * 16 + (lane & 15);
                int col = ks + ((lane & 16) ? 8 : 0);
                ldsm4(aB + (row * LDA + col) * 2, a[mf][0], a[mf][1], a[mf][2], a[mf][3]);
            }
            unsigned bb[8][2];
#pragma unroll
            for (int g = 0; g < 4; g++) {
                int kk = ks + (lane & 15);
                int nn = warpCol + g * 16 + ((lane & 16) ? 8 : 0);
                unsigned r0, r1, r2, r3;
                ldsm4t(bB + (kk * LDB + nn) * 2, r0, r1, r2, r3);
                bb[2 * g][0] = r0; bb[2 * g][1] = r1;
                bb[2 * g + 1][0] = r2; bb[2 * g + 1][1] = r3;
            }
#pragma unroll
            for (int mf = 0; mf < 2; mf++)
#pragma unroll
                for (int nf = 0; nf < 8; nf++)
                    mma16816(acc[mf][nf][0], acc[mf][nf][1], acc[mf][nf][2], acc[mf][nf][3],
                             a[mf][0], a[mf][1], a[mf][2], a[mf][3],
                             bb[nf][0], bb[nf][1]);
        }

        int nx = s + 2;
        if (nx < nsteps) load_stage(nx % 3, nx * 32);
        cp_commit();
        cp_wait1();
        __syncthreads();
    }

    // ---- epilogue: fp16 C stores ----
#pragma unroll
    for (int mf = 0; mf < 2; mf++) {
#pragma unroll
        for (int nf = 0; nf < 8; nf++) {
            int gr0 = rowBase + warpRow + mf * 16 + (lane >> 2);
            int gc  = warpCol + nf * 8 + (lane & 3) * 2;
#pragma unroll
            for (int half = 0; half < 2; half++) {
                int gr = gr0 + half * 8;
                if (gr >= M) continue;
                __half2 hv = __floats2half2_rn(acc[mf][nf][half * 2],
                                               acc[mf][nf][half * 2 + 1]);
                *(__half2*)(C + (size_t)gr * 256 + gc) = hv;
            }
        }
    }

    // ---- fused attention dot products + per-head global max ----
    float av[16], dv[16];
#pragma unroll
    for (int nf = 0; nf < 8; nf++) {
        int gc = warpCol + nf * 8 + (lane & 3) * 2;
        av[nf * 2 + 0] = asrc[gc];     av[nf * 2 + 1] = asrc[gc + 1];
        dv[nf * 2 + 0] = adst[gc];     dv[nf * 2 + 1] = adst[gc + 1];
    }
    float smax = -1e30f;
#pragma unroll
    for (int mf = 0; mf < 2; mf++) {
#pragma unroll
        for (int half = 0; half < 2; half++) {
            int gr = rowBase + warpRow + mf * 16 + (lane >> 2) + half * 8;
            float s = 0.f, d = 0.f;
#pragma unroll
            for (int nf = 0; nf < 8; nf++) {
                float v0 = acc[mf][nf][half * 2], v1 = acc[mf][nf][half * 2 + 1];
                s += v0 * av[nf * 2] + v1 * av[nf * 2 + 1];
                d += v0 * dv[nf * 2] + v1 * dv[nf * 2 + 1];
            }
            s += __shfl_xor_sync(0xffffffffu, s, 1);
            s += __shfl_xor_sync(0xffffffffu, s, 2);
            d += __shfl_xor_sync(0xffffffffu, d, 1);
            d += __shfl_xor_sync(0xffffffffu, d, 2);
            smax = fmaxf(smax, s);   // rows >= M replicate row M-1 (A clamp) -> safe
            if ((lane & 3) == 0 && gr < M) {
                gas[gr * 4 + wn] = s;
                gad[gr * 4 + wn] = d;
            }
        }
    }
    for (int o = 16; o; o >>= 1) smax = fmaxf(smax, __shfl_xor_sync(0xffffffffu, smax, o));
    if (lane == 0) atomicMaxF(&gmax[wn], smax);
}

// ---------------- mma.sync bf16 GEMM (final fused MLP, sigmoid out) ----------------
template <int BN, int WM, int MF>
__global__ __launch_bounds__(256)
void k_gmma(const bf16* __restrict__ A, const bf16* __restrict__ B,
            const float* __restrict__ bias, float* __restrict__ C,
            int M, int Kext, int NB, int Nlog) {
    constexpr int LDA = 40;
    constexpr int LDB = BN + 8;
    constexpr int NB4 = BN * 32 / 2048;

    __shared__ bf16 As[2][128 * LDA];
    __shared__ bf16 Bs[2][32 * LDB];

    const int tid = threadIdx.x;
    const int warp = tid >> 5, lane = tid & 31;
    const int wm = warp % WM, wn = warp / WM;
    const int warpRow = wm * (MF * 16);
    const int warpCol = wn * 64;
    const int rowBase = blockIdx.y * 128;
    const int colBase = blockIdx.x * BN;

    float acc[MF][8][4];
#pragma unroll
    for (int i = 0; i < MF; i++)
#pragma unroll
        for (int j = 0; j < 8; j++)
#pragma unroll
            for (int q = 0; q < 4; q++) acc[i][j][q] = 0.f;

    const int nsteps = Kext / 32;
    int4 pa[2], pb[NB4];

#pragma unroll
    for (int i = 0; i < 2; i++) {
        int idx = tid + i * 256;
        int row = idx >> 2, q = idx & 3;
        int gr = rowBase + row;
        int4 v = (gr < M) ? *(const int4*)(A + (size_t)gr * Kext + q * 8)
                          : make_int4(0, 0, 0, 0);
        *(int4*)(&As[0][row * LDA + q * 8]) = v;
    }
#pragma unroll
    for (int i = 0; i < NB4; i++) {
        int idx = tid + i * 256;
        int k = idx / (BN / 8), q = idx % (BN / 8);
        int4 v = *(const int4*)(B + (size_t)k * NB + colBase + q * 8);
        *(int4*)(&Bs[0][k * LDB + q * 8]) = v;
    }
    __syncthreads();

    for (int s = 0; s < nsteps; ++s) {
        int buf = s & 1;
        bool more = (s + 1 < nsteps);
        int k0n = (s + 1) * 32;

        if (more) {
#pragma unroll
            for (int i = 0; i < 2; i++) {
                int idx = tid + i * 256;
                int row = idx >> 2, q = idx & 3;
                int gr = rowBase + row;
                pa[i] = (gr < M) ? *(const int4*)(A + (size_t)gr * Kext + k0n + q * 8)
                                 : make_int4(0, 0, 0, 0);
            }
#pragma unroll
            for (int i = 0; i < NB4; i++) {
                int idx = tid + i * 256;
                int k = idx / (BN / 8), q = idx % (BN / 8);
                pb[i] = *(const int4*)(B + (size_t)(k0n + k) * NB + colBase + q * 8);
            }
        }

        unsigned aB = smem_u32(&As[buf][0]);
        unsigned bB = smem_u32(&Bs[buf][0]);

#pragma unroll
        for (int ks = 0; ks < 32; ks += 16) {
            unsigned a[MF][4];
#pragma unroll
            for (int mf = 0; mf < MF; mf++) {
                int row = warpRow + mf * 16 + (lane & 15);
                int col = ks + ((lane & 16) ? 8 : 0);
                ldsm4(aB + (row * LDA + col) * 2, a[mf][0], a[mf][1], a[mf][2], a[mf][3]);
            }
            unsigned bb[8][2];
#pragma unroll
            for (int g = 0; g < 4; g++) {
                int kk = ks + (lane & 15);
                int nn = warpCol + g * 16 + ((lane & 16) ? 8 : 0);
                unsigned r0, r1, r2, r3;
                ldsm4t(bB + (kk * LDB + nn) * 2, r0, r1, r2, r3);
                bb[2 * g][0] = r0; bb[2 * g][1] = r1;
                bb[2 * g + 1][0] = r2; bb[2 * g + 1][1] = r3;
            }
#pragma unroll
            for (int mf = 0; mf < MF; mf++)
#pragma unroll
                for (int nf = 0; nf < 8; nf++)
                    mma16816(acc[mf][nf][0], acc[mf][nf][1], acc[mf][nf][2], acc[mf][nf][3],
                             a[mf][0], a[mf][1], a[mf][2], a[mf][3],
                             bb[nf][0], bb[nf][1]);
        }

        if (more) {
            int nb = buf ^ 1;
#pragma unroll
            for (int i = 0; i < 2; i++) {
                int idx = tid + i * 256;
                int row = idx >> 2, q = idx & 3;
                *(int4*)(&As[nb][row * LDA + q * 8]) = pa[i];
            }
#pragma unroll
            for (int i = 0; i < NB4; i++) {
                int idx = tid + i * 256;
                int k = idx / (BN / 8), q = idx % (BN / 8);
                *(int4*)(&Bs[nb][k * LDB + q * 8]) = pb[i];
            }
        }
        __syncthreads();
    }

#pragma unroll
    for (int mf = 0; mf < MF; mf++) {
#pragma unroll
        for (int nf = 0; nf < 8; nf++) {
            int gr0 = rowBase + warpRow + mf * 16 + (lane >> 2);
            int gc  = colBase + warpCol + nf * 8 + (lane & 3) * 2;
#pragma unroll
            for (int half = 0; half < 2; half++) {
                int gr = gr0 + half * 8;
                if (gr >= M) continue;
                float v0 = acc[mf][nf][half * 2 + 0];
                float v1 = acc[mf][nf][half * 2 + 1];
                if (gc < Nlog)
                    C[(size_t)gr * Nlog + gc] = 1.f / (1.f + __expf(-(v0 + bias[gc])));
                if (gc + 1 < Nlog)
                    C[(size_t)gr * Nlog + gc + 1] = 1.f / (1.f + __expf(-(v1 + bias[gc + 1])));
            }
        }
    }
}

// ---------------- launch ----------------
extern "C" void kernel_launch(void* const* d_in, const int* in_sizes, int n_in,
                              void* d_out, int out_size) {
    const float* x   = (const float*)d_in[0];
    const void*  ei  = d_in[1];
    const float* W1  = (const float*)d_in[2];
    const float* as1 = (const float*)d_in[3];
    const float* ad1 = (const float*)d_in[4];
    const float* b1  = (const float*)d_in[5];
    const float* W2  = (const float*)d_in[6];
    const float* as2 = (const float*)d_in[7];
    const float* ad2 = (const float*)d_in[8];
    const float* b2  = (const float*)d_in[9];
    const float* Wm1 = (const float*)d_in[10];
    const float* bm1 = (const float*)d_in[11];
    const float* Wm2 = (const float*)d_in[12];
    const float* bm2 = (const float*)d_in[13];
    float* out = (float*)d_out;

    void* cntp; cudaGetSymbolAddress(&cntp, g_cnt);
    bf16 *ax, *aext, *b1e, *b2e, *bWc;
    __half* h1;
    float *gas, *gad, *bc, *gmax;
    cudaGetSymbolAddress((void**)&ax, g_ax);
    cudaGetSymbolAddress((void**)&aext, g_aext);
    cudaGetSymbolAddress((void**)&h1, g_h1);
    cudaGetSymbolAddress((void**)&gas, g_as);
    cudaGetSymbolAddress((void**)&gad, g_ad);
    cudaGetSymbolAddress((void**)&b1e, g_b1e);
    cudaGetSymbolAddress((void**)&b2e, g_b2e);
    cudaGetSymbolAddress((void**)&bWc, g_bWc);
    cudaGetSymbolAddress((void**)&bc, g_bc);
    cudaGetSymbolAddress((void**)&gmax, g_gmax);

    static cudaStream_t s2 = nullptr;
    static cudaEvent_t ev1 = nullptr, ev2 = nullptr;
    if (!s2) {
        cudaStreamCreateWithFlags(&s2, cudaStreamNonBlocking);
        cudaEventCreateWithFlags(&ev1, cudaEventDisableTiming);
        cudaEventCreateWithFlags(&ev2, cudaEventDisableTiming);
    }

    const int MB = (Nn + 127) / 128;  // 391
    const int G256_SMEM = 3 * (128 * 40 + 32 * 264) * (int)sizeof(bf16);  // 81408
    cudaFuncSetAttribute(k_g256, cudaFuncAttributeMaxDynamicSharedMemorySize, G256_SMEM);

    // ---- fork point for CSR side-stream ----
    cudaEventRecord(ev1, 0);

    // ---- main stream ----
    k_convA<<<(Nn * 128 + 255) / 256, 256>>>(x, ax, Nn, 128);
    k_convB<<<(128 * 256 + 255) / 256, 256>>>(W1, b1e, 128, 256, 256);
    k_convB<<<(256 * 256 + 255) / 256, 256>>>(W2, b2e, 256, 256, 256);
    k_rst<<<1, 32>>>();
    k_g256<<<dim3(1, MB), 512, G256_SMEM>>>(ax, b1e, h1, Nn, 256,
                                            as1, ad1, gas, gad, gmax);
    k_fuse<<<(256 * 128 + 255) / 256, 256>>>(Wm1, bm1, Wm2, bm2, bWc, bc);

    // ---- side stream: CSR build ----
    cudaStreamWaitEvent(s2, ev1, 0);
    k_detect<<<1, 256, 0, s2>>>((const long long*)ei);
    cudaMemsetAsync(cntp, 0, Nn * sizeof(int), s2);
    k_hist<<<(ETOT + 255) / 256, 256, 0, s2>>>(ei);
    k_scan_block<<<49, 1024, 0, s2>>>();
    k_scan_bsum<<<1, 64, 0, s2>>>(49);
    k_scan_add<<<49, 1024, 0, s2>>>();
    cudaMemsetAsync(cntp, 0, Nn * sizeof(int), s2);
    k_scatter<<<(ETOT + 255) / 256, 256, 0, s2>>>(ei);
    cudaEventRecord(ev2, s2);

    // ---- join ----
    cudaStreamWaitEvent(0, ev2, 0);
    k_agg4<<<Nn, 128>>>(h1, b1, aext);
    // ---- layer 2 ----
    k_rst<<<1, 32>>>();
    k_g256<<<dim3(1, MB), 512, G256_SMEM>>>(aext, b2e, h1, Nn, 512,
                                            as2, ad2, gas, gad, gmax);
    k_agg4<<<Nn, 128>>>(h1, b2, aext);
    // ---- fused MLP head ----
    k_gmma<128, 4, 2><<<dim3(1, MB), 256>>>(aext, bWc, bc, out, Nn, 512, 128, 121);
}